// round 1
// baseline (speedup 1.0000x reference)
#include <cuda_runtime.h>
#include <cstdint>

// ---------------------------------------------------------------------------
// GCN: h1 = relu(spmm(x@W1)+b1); h2 = relu(spmm(h1@W2)+b2);
//      h3 = relu(spmm(h2@W3)+b3); y = softmax(relu(mean(h3)@fc1+b)@fc2+b)
// relu is folded into the consumer of each h (next gemm / pool).
// Scratch: static __device__ arrays (no runtime allocation).
// ---------------------------------------------------------------------------

#define MAXN 100000

__device__ __align__(16) float g_s[(size_t)MAXN * 64];   // gemm output (support)
__device__ __align__(16) float g_h[(size_t)MAXN * 64];   // spmm output (hidden)
__device__ float g_ysum[64];

// ---- packed f32x2 helpers (Blackwell) -------------------------------------
__device__ __forceinline__ unsigned long long splat2(float x) {
    unsigned long long r;
    asm("mov.b64 %0, {%1, %1};" : "=l"(r) : "f"(x));
    return r;
}
__device__ __forceinline__ void ffma2(unsigned long long& acc,
                                      unsigned long long w,
                                      unsigned long long x2) {
    asm("fma.rn.f32x2 %0, %1, %2, %0;" : "+l"(acc) : "l"(w), "l"(x2));
}
__device__ __forceinline__ float2 unpack2(unsigned long long v) {
    float2 f;
    asm("mov.b64 {%0, %1}, %2;" : "=f"(f.x), "=f"(f.y) : "l"(v));
    return f;
}

// ---------------------------------------------------------------------------
// GEMM: Y[n,OUT] = (RELU? relu(X) : X)[n,IN] @ W[IN,OUT]
// One thread per node row; W staged in smem, read as ulonglong2 (2x f32x2).
// FROM_PARAM: layer 1 reads the external x; else reads g_h (with relu).
// Always writes g_s.
// ---------------------------------------------------------------------------
template <int IN, int OUT, bool FROM_PARAM>
__global__ void __launch_bounds__(256)
gemm_kernel(const float* __restrict__ Xparam, const float* __restrict__ W, int n) {
    __shared__ __align__(16) float Wsh[IN * OUT];
    for (int i = threadIdx.x; i < IN * OUT; i += 256) Wsh[i] = W[i];
    __syncthreads();

    int node = blockIdx.x * 256 + threadIdx.x;
    if (node >= n) return;

    const float* __restrict__ X = FROM_PARAM ? Xparam : (const float*)g_h;

    unsigned long long acc[OUT / 2];
#pragma unroll
    for (int j = 0; j < OUT / 2; j++) acc[j] = 0ull;

    const float4* __restrict__ Xv = (const float4*)(X + (size_t)node * IN);
    const ulonglong2* __restrict__ Wv = (const ulonglong2*)Wsh;

    for (int k4 = 0; k4 < IN / 4; k4++) {
        float4 xv = Xv[k4];
        if (!FROM_PARAM) {  // relu on hidden input
            xv.x = fmaxf(xv.x, 0.f); xv.y = fmaxf(xv.y, 0.f);
            xv.z = fmaxf(xv.z, 0.f); xv.w = fmaxf(xv.w, 0.f);
        }
        float xs[4] = {xv.x, xv.y, xv.z, xv.w};
#pragma unroll
        for (int kk = 0; kk < 4; kk++) {
            unsigned long long x2 = splat2(xs[kk]);
            int k = k4 * 4 + kk;
#pragma unroll
            for (int j = 0; j < OUT / 4; j++) {
                ulonglong2 w = Wv[k * (OUT / 4) + j];
                ffma2(acc[2 * j + 0], w.x, x2);
                ffma2(acc[2 * j + 1], w.y, x2);
            }
        }
    }

    float4* __restrict__ Yv = (float4*)((float*)g_s + (size_t)node * OUT);
#pragma unroll
    for (int j = 0; j < OUT / 4; j++) {
        float2 a = unpack2(acc[2 * j + 0]);
        float2 b = unpack2(acc[2 * j + 1]);
        Yv[j] = make_float4(a.x, a.y, b.x, b.y);
    }
}

// ---------------------------------------------------------------------------
// init: g_h[i][f] = b[f]  (spmm accumulates on top); optionally zero g_ysum
// ---------------------------------------------------------------------------
template <int F, bool ZERO_YSUM>
__global__ void __launch_bounds__(256)
init_bias_kernel(const float* __restrict__ b, int n) {
    if (ZERO_YSUM && blockIdx.x == 0 && threadIdx.x < 64) g_ysum[threadIdx.x] = 0.f;
    __shared__ __align__(16) float bs[F];
    if (threadIdx.x < F) bs[threadIdx.x] = b[threadIdx.x];
    __syncthreads();
    const float4* bv = (const float4*)bs;
    float4* Hv = (float4*)g_h;
    int total = n * (F / 4);
    for (int i = blockIdx.x * 256 + threadIdx.x; i < total; i += gridDim.x * 256)
        Hv[i] = bv[i % (F / 4)];
}

// ---------------------------------------------------------------------------
// SpMM: g_h[row[e]] += ev[e] * g_s[col[e]]   (F = 4*F4 floats per row)
// One thread handles one (edge, 4-feature chunk): float4 gather + red.v4.
// ---------------------------------------------------------------------------
template <int F4>
__global__ void __launch_bounds__(256)
spmm_kernel(const int* __restrict__ row, const int* __restrict__ col,
            const float* __restrict__ ev, int E) {
    int tid = blockIdx.x * 256 + threadIdx.x;
    int e = tid / F4;
    if (e >= E) return;
    int c = tid - e * F4;
    int r = __ldg(&row[e]);
    int cl = __ldg(&col[e]);
    float v = __ldg(&ev[e]);
    const float4 s = *(const float4*)((const float*)g_s + (size_t)cl * (4 * F4) + 4 * c);
    float* dst = (float*)g_h + (size_t)r * (4 * F4) + 4 * c;
    float p0 = s.x * v, p1 = s.y * v, p2 = s.z * v, p3 = s.w * v;
    asm volatile("red.global.add.v4.f32 [%0], {%1,%2,%3,%4};"
                 :: "l"(dst), "f"(p0), "f"(p1), "f"(p2), "f"(p3)
                 : "memory");
}

// ---------------------------------------------------------------------------
// pool: g_ysum[f] += sum_nodes relu(g_h[node][f])   (F=64)
// ---------------------------------------------------------------------------
__global__ void __launch_bounds__(256)
pool_kernel(int n) {
    int f = threadIdx.x & 63;
    int sub = threadIdx.x >> 6;  // 0..3
    float acc = 0.f;
    for (int node = blockIdx.x * 4 + sub; node < n; node += gridDim.x * 4)
        acc += fmaxf(g_h[(size_t)node * 64 + f], 0.f);
    __shared__ float sh[256];
    sh[threadIdx.x] = acc;
    __syncthreads();
    if (threadIdx.x < 64) {
        float s = sh[threadIdx.x] + sh[threadIdx.x + 64] +
                  sh[threadIdx.x + 128] + sh[threadIdx.x + 192];
        atomicAdd(&g_ysum[threadIdx.x], s);
    }
}

// ---------------------------------------------------------------------------
// head: y = ysum/N; z1 = relu(y@fc1W + fc1b); out = softmax(z1@fc2W + fc2b)
// ---------------------------------------------------------------------------
__global__ void head_kernel(const float* __restrict__ fc1W, const float* __restrict__ fc1b,
                            const float* __restrict__ fc2W, const float* __restrict__ fc2b,
                            float* __restrict__ out, float invN) {
    __shared__ float y[64];
    __shared__ float z1[32];
    __shared__ float z2[2];
    int t = threadIdx.x;
    y[t] = g_ysum[t] * invN;
    __syncthreads();
    if (t < 32) {
        float a = fc1b[t];
#pragma unroll
        for (int i = 0; i < 64; i++) a = fmaf(y[i], fc1W[i * 32 + t], a);
        z1[t] = fmaxf(a, 0.f);
    }
    __syncthreads();
    if (t < 2) {
        float a = fc2b[t];
#pragma unroll
        for (int i = 0; i < 32; i++) a = fmaf(z1[i], fc2W[i * 2 + t], a);
        z2[t] = a;
    }
    __syncthreads();
    if (t == 0) {
        float m = fmaxf(z2[0], z2[1]);
        float e0 = __expf(z2[0] - m), e1 = __expf(z2[1] - m);
        float inv = 1.f / (e0 + e1);
        out[0] = e0 * inv;
        out[1] = e1 * inv;
    }
}

// ---------------------------------------------------------------------------
extern "C" void kernel_launch(void* const* d_in, const int* in_sizes, int n_in,
                              void* d_out, int out_size) {
    const float* x    = (const float*)d_in[0];
    const int*   row  = (const int*)d_in[1];
    const int*   col  = (const int*)d_in[2];
    const float* ev   = (const float*)d_in[3];
    const float* W1   = (const float*)d_in[4];
    const float* b1   = (const float*)d_in[5];
    const float* W2   = (const float*)d_in[6];
    const float* b2   = (const float*)d_in[7];
    const float* W3   = (const float*)d_in[8];
    const float* b3   = (const float*)d_in[9];
    const float* fc1W = (const float*)d_in[10];
    const float* fc1b = (const float*)d_in[11];
    const float* fc2W = (const float*)d_in[12];
    const float* fc2b = (const float*)d_in[13];
    float* out = (float*)d_out;

    int N = in_sizes[0] / 256;   // NFEAT = 256
    int E = in_sizes[1];

    int gn = (N + 255) / 256;

    // Layer 1
    gemm_kernel<256, 32, true><<<gn, 256>>>(x, W1, N);
    init_bias_kernel<32, false><<<1024, 256>>>(b1, N);
    {
        long long t = (long long)E * 8;
        spmm_kernel<8><<<(int)((t + 255) / 256), 256>>>(row, col, ev, E);
    }
    // Layer 2 (relu folded into gemm input read)
    gemm_kernel<32, 48, false><<<gn, 256>>>(nullptr, W2, N);
    init_bias_kernel<48, false><<<1024, 256>>>(b2, N);
    {
        long long t = (long long)E * 12;
        spmm_kernel<12><<<(int)((t + 255) / 256), 256>>>(row, col, ev, E);
    }
    // Layer 3
    gemm_kernel<48, 64, false><<<gn, 256>>>(nullptr, W3, N);
    init_bias_kernel<64, true><<<1024, 256>>>(b3, N);
    {
        long long t = (long long)E * 16;
        spmm_kernel<16><<<(int)((t + 255) / 256), 256>>>(row, col, ev, E);
    }
    // Pool + head
    pool_kernel<<<1024, 256>>>(N);
    head_kernel<<<1, 64>>>(fc1W, fc1b, fc2W, fc2b, out, 1.0f / (float)N);
}

// round 2
// speedup vs baseline: 1.2889x; 1.2889x over previous
#include <cuda_runtime.h>
#include <cstdint>

// ---------------------------------------------------------------------------
// GCN, round 2:
//  - Tiled coalesced GEMMs (smem, f32x2 FMA, 64 nodes/block)
//  - Per-launch CSR build (count/scan/fill), then gather-only SpMM with bias
//    folded in (no atomics in hot path)
// ---------------------------------------------------------------------------

#define MAXN 100000
#define MAXE 1600000
#define NB_SCAN ((MAXN + 255) / 256)   // 391

__device__ __align__(16) float g_s[(size_t)MAXN * 64];   // gemm output (support)
__device__ __align__(16) float g_h[(size_t)MAXN * 64];   // spmm output (hidden)
__device__ float g_ysum[64];

// CSR scratch
__device__ int   g_cnt[MAXN];
__device__ int   g_ptr[MAXN];
__device__ int   g_fill[MAXN];
__device__ int   g_bsum[NB_SCAN + 1];
__device__ int   g_boff[512];
__device__ __align__(16) int   g_ecol[MAXE];
__device__ __align__(16) float g_eval[MAXE];

// ---- packed f32x2 helpers -------------------------------------------------
__device__ __forceinline__ unsigned long long splat2(float x) {
    unsigned long long r;
    asm("mov.b64 %0, {%1, %1};" : "=l"(r) : "f"(x));
    return r;
}
__device__ __forceinline__ void ffma2(unsigned long long& acc,
                                      unsigned long long w,
                                      unsigned long long x2) {
    asm("fma.rn.f32x2 %0, %1, %2, %0;" : "+l"(acc) : "l"(w), "l"(x2));
}
__device__ __forceinline__ float2 unpack2(unsigned long long v) {
    float2 f;
    asm("mov.b64 {%0, %1}, %2;" : "=f"(f.x), "=f"(f.y) : "l"(v));
    return f;
}

// ---------------------------------------------------------------------------
// Tiled GEMM: g_s[n,OUT] = act(X)[n,IN] @ W[IN,OUT]
// Block: 256 threads, 64 nodes. K processed in chunks of KC.
// Thread t: node = t&63, outgroup = t>>6 computes OW = OUT/4 outputs.
// Smem: Xs[64][KC+1] (odd stride -> conflict-free), Ws[KC][OUT].
// ---------------------------------------------------------------------------
template <int IN, int OUT, int KC, bool RELU_IN, bool FROM_PARAM>
__global__ void __launch_bounds__(256)
gemm_kernel(const float* __restrict__ Xparam, const float* __restrict__ W, int n) {
    constexpr int OW = OUT / 4;          // outputs per thread (8 / 12 / 16)
    constexpr int XS = KC + 1;           // odd row stride
    __shared__ float Xs[64 * XS];
    __shared__ __align__(16) float Ws[KC * OUT];

    const float* __restrict__ X = FROM_PARAM ? Xparam : (const float*)g_h;

    const int node0 = blockIdx.x * 64;
    const int t = threadIdx.x;
    const int node = t & 63;
    const int outg = t >> 6;
    const int gn = node0 + node;

    unsigned long long acc[OW / 2];
#pragma unroll
    for (int j = 0; j < OW / 2; j++) acc[j] = 0ull;

    for (int c = 0; c < IN / KC; c++) {
        // load X tile (coalesced: consecutive idx -> consecutive k in a row chunk)
        for (int idx = t; idx < 64 * KC; idx += 256) {
            int nd = idx / KC, k = idx % KC;
            int g = node0 + nd;
            float v = (g < n) ? X[(size_t)g * IN + c * KC + k] : 0.f;
            if (RELU_IN) v = fmaxf(v, 0.f);
            Xs[nd * XS + k] = v;
        }
        // load W chunk (contiguous)
        for (int idx = t; idx < KC * OUT; idx += 256)
            Ws[idx] = W[c * KC * OUT + idx];
        __syncthreads();

        const float* xrow = &Xs[node * XS];
#pragma unroll 4
        for (int k = 0; k < KC; k++) {
            unsigned long long x2 = splat2(xrow[k]);
            const ulonglong2* wv =
                (const ulonglong2*)&Ws[k * OUT + outg * OW];
#pragma unroll
            for (int j = 0; j < OW / 4; j++) {
                ulonglong2 w = wv[j];
                ffma2(acc[2 * j + 0], w.x, x2);
                ffma2(acc[2 * j + 1], w.y, x2);
            }
        }
        __syncthreads();
    }

    if (gn < n) {
        float4* dst = (float4*)((float*)g_s + (size_t)gn * OUT + outg * OW);
#pragma unroll
        for (int j = 0; j < OW / 4; j++) {
            float2 a = unpack2(acc[2 * j + 0]);
            float2 b = unpack2(acc[2 * j + 1]);
            dst[j] = make_float4(a.x, a.y, b.x, b.y);
        }
    }
}

// ---------------------------------------------------------------------------
// CSR build
// ---------------------------------------------------------------------------
__global__ void __launch_bounds__(256)
zero_cnt_kernel(int n) {
    int i = blockIdx.x * 256 + threadIdx.x;
    if (i < n) g_cnt[i] = 0;
    if (blockIdx.x == 0 && threadIdx.x < 64) g_ysum[threadIdx.x] = 0.f;
}

__global__ void __launch_bounds__(256)
count_kernel(const int* __restrict__ row, int E) {
    int e = blockIdx.x * 256 + threadIdx.x;
    if (e < E) atomicAdd(&g_cnt[row[e]], 1);
}

// per-block exclusive scan of g_cnt -> g_ptr (partial), block totals -> g_bsum
__global__ void __launch_bounds__(256)
scan1_kernel(int n) {
    __shared__ int s[256];
    int t = threadIdx.x;
    int i = blockIdx.x * 256 + t;
    int v = (i < n) ? g_cnt[i] : 0;
    s[t] = v;
    __syncthreads();
#pragma unroll
    for (int off = 1; off < 256; off <<= 1) {
        int tmp = (t >= off) ? s[t - off] : 0;
        __syncthreads();
        s[t] += tmp;
        __syncthreads();
    }
    if (i < n) g_ptr[i] = s[t] - v;          // exclusive
    if (t == 255) g_bsum[blockIdx.x] = s[255];
}

// single-block exclusive scan of block sums -> g_boff
__global__ void __launch_bounds__(512)
scan2_kernel(int nb) {
    __shared__ int s[512];
    int t = threadIdx.x;
    int v = (t < nb) ? g_bsum[t] : 0;
    s[t] = v;
    __syncthreads();
#pragma unroll
    for (int off = 1; off < 512; off <<= 1) {
        int tmp = (t >= off) ? s[t - off] : 0;
        __syncthreads();
        s[t] += tmp;
        __syncthreads();
    }
    g_boff[t] = s[t] - v;                    // exclusive
}

// fixup + init fill cursors
__global__ void __launch_bounds__(256)
scan3_kernel(int n) {
    int i = blockIdx.x * 256 + threadIdx.x;
    if (i < n) {
        int p = g_ptr[i] + g_boff[blockIdx.x];
        g_ptr[i] = p;
        g_fill[i] = p;
    }
}

__global__ void __launch_bounds__(256)
fill_kernel(const int* __restrict__ row, const int* __restrict__ col,
            const float* __restrict__ ev, int E) {
    int e = blockIdx.x * 256 + threadIdx.x;
    if (e < E) {
        int r = row[e];
        int p = atomicAdd(&g_fill[r], 1);
        g_ecol[p] = col[e];
        g_eval[p] = ev[e];
    }
}

// ---------------------------------------------------------------------------
// Gather SpMM: g_h[i][:] = b[:] + sum_{j in CSR(i)} eval[j] * g_s[ecol[j]][:]
// Thread handles (node, 4-feature chunk c). F = 4*F4.
// ---------------------------------------------------------------------------
template <int F4>
__global__ void __launch_bounds__(256)
spmm_csr_kernel(const float* __restrict__ b, int n) {
    int tid = blockIdx.x * 256 + threadIdx.x;
    int node = tid / F4;
    if (node >= n) return;
    int c = tid - node * F4;

    float4 acc = ((const float4*)b)[c];
    int j = g_ptr[node];
    int end = j + g_cnt[node];
    const float4* __restrict__ S = (const float4*)g_s;

    for (; j < end; j++) {
        int cl = __ldg(&g_ecol[j]);
        float v = __ldg(&g_eval[j]);
        float4 s = S[(size_t)cl * F4 + c];
        acc.x = fmaf(v, s.x, acc.x);
        acc.y = fmaf(v, s.y, acc.y);
        acc.z = fmaf(v, s.z, acc.z);
        acc.w = fmaf(v, s.w, acc.w);
    }
    ((float4*)g_h)[(size_t)node * F4 + c] = acc;
}

// ---------------------------------------------------------------------------
// pool: g_ysum[f] += sum_nodes relu(g_h[node][f])   (F=64)
// ---------------------------------------------------------------------------
__global__ void __launch_bounds__(256)
pool_kernel(int n) {
    int f = threadIdx.x & 63;
    int sub = threadIdx.x >> 6;
    float acc = 0.f;
    for (int node = blockIdx.x * 4 + sub; node < n; node += gridDim.x * 4)
        acc += fmaxf(g_h[(size_t)node * 64 + f], 0.f);
    __shared__ float sh[256];
    sh[threadIdx.x] = acc;
    __syncthreads();
    if (threadIdx.x < 64) {
        float s = sh[threadIdx.x] + sh[threadIdx.x + 64] +
                  sh[threadIdx.x + 128] + sh[threadIdx.x + 192];
        atomicAdd(&g_ysum[threadIdx.x], s);
    }
}

// ---------------------------------------------------------------------------
// head: y = ysum/N; z1 = relu(y@fc1W+fc1b); out = softmax(z1@fc2W+fc2b)
// ---------------------------------------------------------------------------
__global__ void head_kernel(const float* __restrict__ fc1W, const float* __restrict__ fc1b,
                            const float* __restrict__ fc2W, const float* __restrict__ fc2b,
                            float* __restrict__ out, float invN) {
    __shared__ float y[64];
    __shared__ float z1[32];
    __shared__ float z2[2];
    int t = threadIdx.x;
    y[t] = g_ysum[t] * invN;
    __syncthreads();
    if (t < 32) {
        float a = fc1b[t];
#pragma unroll
        for (int i = 0; i < 64; i++) a = fmaf(y[i], fc1W[i * 32 + t], a);
        z1[t] = fmaxf(a, 0.f);
    }
    __syncthreads();
    if (t < 2) {
        float a = fc2b[t];
#pragma unroll
        for (int i = 0; i < 32; i++) a = fmaf(z1[i], fc2W[i * 2 + t], a);
        z2[t] = a;
    }
    __syncthreads();
    if (t == 0) {
        float m = fmaxf(z2[0], z2[1]);
        float e0 = __expf(z2[0] - m), e1 = __expf(z2[1] - m);
        float inv = 1.f / (e0 + e1);
        out[0] = e0 * inv;
        out[1] = e1 * inv;
    }
}

// ---------------------------------------------------------------------------
extern "C" void kernel_launch(void* const* d_in, const int* in_sizes, int n_in,
                              void* d_out, int out_size) {
    const float* x    = (const float*)d_in[0];
    const int*   row  = (const int*)d_in[1];
    const int*   col  = (const int*)d_in[2];
    const float* ev   = (const float*)d_in[3];
    const float* W1   = (const float*)d_in[4];
    const float* b1   = (const float*)d_in[5];
    const float* W2   = (const float*)d_in[6];
    const float* b2   = (const float*)d_in[7];
    const float* W3   = (const float*)d_in[8];
    const float* b3   = (const float*)d_in[9];
    const float* fc1W = (const float*)d_in[10];
    const float* fc1b = (const float*)d_in[11];
    const float* fc2W = (const float*)d_in[12];
    const float* fc2b = (const float*)d_in[13];
    float* out = (float*)d_out;

    int N = in_sizes[0] / 256;   // NFEAT = 256
    int E = in_sizes[1];

    int nbN  = (N + 255) / 256;          // 391
    int nbE  = (E + 255) / 256;          // 6250
    int gG   = (N + 63) / 64;            // 1563 gemm blocks

    // ---- CSR build (per launch, idempotent) ----
    zero_cnt_kernel<<<nbN, 256>>>(N);
    count_kernel<<<nbE, 256>>>(row, E);
    scan1_kernel<<<nbN, 256>>>(N);
    scan2_kernel<<<1, 512>>>(nbN);
    scan3_kernel<<<nbN, 256>>>(N);
    fill_kernel<<<nbE, 256>>>(row, col, ev, E);

    // ---- Layer 1: x[.,256] @ W1 -> spmm (+b1) ----
    gemm_kernel<256, 32, 64, false, true><<<gG, 256>>>(x, W1, N);
    spmm_csr_kernel<8><<<(N * 8 + 255) / 256, 256>>>(b1, N);

    // ---- Layer 2: relu(h) @ W2 -> spmm (+b2) ----
    gemm_kernel<32, 48, 32, true, false><<<gG, 256>>>(nullptr, W2, N);
    spmm_csr_kernel<12><<<(N * 12 + 255) / 256, 256>>>(b2, N);

    // ---- Layer 3: relu(h) @ W3 -> spmm (+b3) ----
    gemm_kernel<48, 64, 48, true, false><<<gG, 256>>>(nullptr, W3, N);
    spmm_csr_kernel<16><<<(N * 16 + 255) / 256, 256>>>(b3, N);

    // ---- pool + head ----
    pool_kernel<<<1024, 256>>>(N);
    head_kernel<<<1, 64>>>(fc1W, fc1b, fc2W, fc2b, out, 1.0f / (float)N);
}

// round 4
// speedup vs baseline: 1.3951x; 1.0824x over previous
#include <cuda_runtime.h>
#include <cuda_fp16.h>
#include <cstdint>

// ---------------------------------------------------------------------------
// GCN, round 3:
//  - support matrix g_s stored fp16 (halves SpMM gather traffic), fp32 accum
//  - SpMM: 8-lane groups per node, half2 vector gathers, packed 8B edge recs
//  - layer-3 SpMM fused with global mean pool (h3 never materialized)
//  - CSR build: count fused into gemm1 launch, 1-warp block-sum scan
// ---------------------------------------------------------------------------

#define MAXN 100000
#define MAXE 1600000
#define NB_SCAN ((MAXN + 255) / 256)   // 391

__device__ __align__(16) __half g_s16[(size_t)MAXN * 64];  // gemm out (fp16)
__device__ __align__(16) float  g_h[(size_t)MAXN * 64];    // spmm out (fp32)
__device__ float g_ysum[64];

// CSR scratch
__device__ int g_cnt[MAXN];
__device__ int g_ptr[MAXN];
__device__ int g_fill[MAXN];
__device__ int g_bsum[NB_SCAN + 1];
__device__ int g_boff[NB_SCAN + 1];
__device__ __align__(16) long long g_epack[MAXE];   // (val<<32)|col

// ---- packed f32x2 helpers -------------------------------------------------
__device__ __forceinline__ unsigned long long splat2(float x) {
    unsigned long long r;
    asm("mov.b64 %0, {%1, %1};" : "=l"(r) : "f"(x));
    return r;
}
__device__ __forceinline__ void ffma2(unsigned long long& acc,
                                      unsigned long long w,
                                      unsigned long long x2) {
    asm("fma.rn.f32x2 %0, %1, %2, %0;" : "+l"(acc) : "l"(w), "l"(x2));
}
__device__ __forceinline__ float2 unpack2(unsigned long long v) {
    float2 f;
    asm("mov.b64 {%0, %1}, %2;" : "=f"(f.x), "=f"(f.y) : "l"(v));
    return f;
}

// ---------------------------------------------------------------------------
// Tiled GEMM body: g_s16[n,OUT] = act(X)[n,IN] @ W[IN,OUT]   (fp32 -> fp16)
// 256 threads, 64 nodes/block; thread t: node=t&63, outg=t>>6 owns OW cols.
// ---------------------------------------------------------------------------
template <int IN, int OUT, int KC, bool RELU_IN, bool FROM_PARAM>
__device__ __forceinline__ void gemm_body(const float* __restrict__ Xparam,
                                          const float* __restrict__ W,
                                          int n, int bid) {
    constexpr int OW = OUT / 4;
    constexpr int XS = KC + 1;
    __shared__ float Xs[64 * XS];
    __shared__ __align__(16) float Ws[KC * OUT];

    const float* __restrict__ X = FROM_PARAM ? Xparam : (const float*)g_h;

    const int node0 = bid * 64;
    const int t = threadIdx.x;
    const int node = t & 63;
    const int outg = t >> 6;
    const int gn = node0 + node;

    unsigned long long acc[OW / 2];
#pragma unroll
    for (int j = 0; j < OW / 2; j++) acc[j] = 0ull;

    for (int c = 0; c < IN / KC; c++) {
        for (int idx = t; idx < 64 * KC; idx += 256) {
            int nd = idx / KC, k = idx % KC;
            int g = node0 + nd;
            float v = (g < n) ? X[(size_t)g * IN + c * KC + k] : 0.f;
            if (RELU_IN) v = fmaxf(v, 0.f);
            Xs[nd * XS + k] = v;
        }
        for (int idx = t; idx < KC * OUT; idx += 256)
            Ws[idx] = W[c * KC * OUT + idx];
        __syncthreads();

        const float* xrow = &Xs[node * XS];
#pragma unroll 4
        for (int k = 0; k < KC; k++) {
            unsigned long long x2 = splat2(xrow[k]);
            const ulonglong2* wv = (const ulonglong2*)&Ws[k * OUT + outg * OW];
#pragma unroll
            for (int j = 0; j < OW / 4; j++) {
                ulonglong2 w = wv[j];
                ffma2(acc[2 * j + 0], w.x, x2);
                ffma2(acc[2 * j + 1], w.y, x2);
            }
        }
        __syncthreads();
    }

    if (gn < n) {
        __half2* dst = (__half2*)(g_s16 + (size_t)gn * OUT) + outg * (OW / 2);
#pragma unroll
        for (int j = 0; j < OW / 4; j++) {
            float2 a = unpack2(acc[2 * j + 0]);
            float2 b = unpack2(acc[2 * j + 1]);
            dst[2 * j + 0] = __floats2half2_rn(a.x, a.y);
            dst[2 * j + 1] = __floats2half2_rn(b.x, b.y);
        }
    }
}

// gemm1 fused with degree-count (independent; overlaps DRAM gemm w/ atomics)
__global__ void __launch_bounds__(256)
gemm1_count_kernel(const float* __restrict__ x, const float* __restrict__ W1,
                   const int* __restrict__ row, int n, int gG, int E) {
    if (blockIdx.x < gG) {
        gemm_body<256, 32, 64, false, true>(x, W1, n, blockIdx.x);
        return;
    }
    int e0 = ((blockIdx.x - gG) * 256 + threadIdx.x) * 4;
    if (e0 + 3 < E) {
        int4 r = *(const int4*)(row + e0);
        atomicAdd(&g_cnt[r.x], 1);
        atomicAdd(&g_cnt[r.y], 1);
        atomicAdd(&g_cnt[r.z], 1);
        atomicAdd(&g_cnt[r.w], 1);
    } else {
        for (int e = e0; e < E; e++) atomicAdd(&g_cnt[row[e]], 1);
    }
}

template <int IN, int OUT, int KC, bool RELU_IN, bool FROM_PARAM>
__global__ void __launch_bounds__(256)
gemm_kernel(const float* __restrict__ Xparam, const float* __restrict__ W, int n) {
    gemm_body<IN, OUT, KC, RELU_IN, FROM_PARAM>(Xparam, W, n, blockIdx.x);
}

// ---------------------------------------------------------------------------
// CSR build
// ---------------------------------------------------------------------------
__global__ void __launch_bounds__(256)
zero_cnt_kernel(int n) {
    int i = blockIdx.x * 256 + threadIdx.x;
    if (i < n) g_cnt[i] = 0;
    if (blockIdx.x == 0 && threadIdx.x < 64) g_ysum[threadIdx.x] = 0.f;
}

__global__ void __launch_bounds__(256)
scan1_kernel(int n) {
    __shared__ int s[256];
    int t = threadIdx.x;
    int i = blockIdx.x * 256 + t;
    int v = (i < n) ? g_cnt[i] : 0;
    s[t] = v;
    __syncthreads();
#pragma unroll
    for (int off = 1; off < 256; off <<= 1) {
        int tmp = (t >= off) ? s[t - off] : 0;
        __syncthreads();
        s[t] += tmp;
        __syncthreads();
    }
    if (i < n) g_ptr[i] = s[t] - v;
    if (t == 255) g_bsum[blockIdx.x] = s[255];
}

__global__ void scan2_kernel(int nb) {   // 1 warp
    int t = threadIdx.x;
    int carry = 0;
    for (int base = 0; base < nb; base += 32) {
        int i = base + t;
        int v = (i < nb) ? g_bsum[i] : 0;
        int s = v;
#pragma unroll
        for (int off = 1; off < 32; off <<= 1) {
            int u = __shfl_up_sync(0xffffffffu, s, off);
            if (t >= off) s += u;
        }
        if (i < nb) g_boff[i] = carry + s - v;
        carry += __shfl_sync(0xffffffffu, s, 31);
    }
}

__global__ void __launch_bounds__(256)
scan3_kernel(int n) {
    int i = blockIdx.x * 256 + threadIdx.x;
    if (i < n) {
        int p = g_ptr[i] + g_boff[blockIdx.x];
        g_ptr[i] = p;
        g_fill[i] = p;
    }
}

__global__ void __launch_bounds__(256)
fill_kernel(const int* __restrict__ row, const int* __restrict__ col,
            const float* __restrict__ ev, int E) {
    int e = blockIdx.x * 256 + threadIdx.x;
    if (e < E) {
        int p = atomicAdd(&g_fill[row[e]], 1);
        g_epack[p] = ((long long)__float_as_int(ev[e]) << 32) |
                     (unsigned int)col[e];
    }
}

// ---------------------------------------------------------------------------
// SpMM (layers 1,2): 8-lane group per node; lane l owns cols {16c+2l, +1}.
// g_h[node] = b + sum_j val_j * fp16(g_s16[col_j])        (fp32 accumulate)
// ---------------------------------------------------------------------------
template <int F>
__global__ void __launch_bounds__(256)
spmm_kernel(const float* __restrict__ b, int n) {
    constexpr int C = F / 16;
    int gid = (blockIdx.x * 256 + threadIdx.x) >> 3;
    int l = threadIdx.x & 7;
    if (gid >= n) return;

    float2 acc[C];
#pragma unroll
    for (int c = 0; c < C; c++)
        acc[c] = *(const float2*)(b + 16 * c + 2 * l);

    int j = g_ptr[gid];
    int end = j + g_cnt[gid];
    const __half2* __restrict__ S = (const __half2*)g_s16;

    for (; j < end; j++) {
        long long ep = __ldg(&g_epack[j]);
        int cl = (int)ep;
        float v = __int_as_float((int)(ep >> 32));
        const __half2* rowp = S + (size_t)cl * (F / 2) + l;
#pragma unroll
        for (int c = 0; c < C; c++) {
            float2 s = __half22float2(rowp[8 * c]);
            acc[c].x = fmaf(v, s.x, acc[c].x);
            acc[c].y = fmaf(v, s.y, acc[c].y);
        }
    }

    float2* H = (float2*)(g_h + (size_t)gid * F);
#pragma unroll
    for (int c = 0; c < C; c++) H[8 * c + l] = acc[c];
}

// ---------------------------------------------------------------------------
// Layer-3 SpMM fused with mean pool (F=64): never materializes h3.
// ---------------------------------------------------------------------------
__global__ void __launch_bounds__(256)
spmm3_pool_kernel(const float* __restrict__ b, int n) {
    constexpr int C = 4;   // F = 64
    int l = threadIdx.x & 7;
    int g = threadIdx.x >> 3;        // group in block, 0..31
    const __half2* __restrict__ S = (const __half2*)g_s16;

    float2 bias[C], ys[C];
#pragma unroll
    for (int c = 0; c < C; c++) {
        bias[c] = *(const float2*)(b + 16 * c + 2 * l);
        ys[c] = make_float2(0.f, 0.f);
    }

    for (int node = blockIdx.x * 32 + g; node < n; node += gridDim.x * 32) {
        float2 acc[C];
#pragma unroll
        for (int c = 0; c < C; c++) acc[c] = bias[c];

        int j = g_ptr[node];
        int end = j + g_cnt[node];
        for (; j < end; j++) {
            long long ep = __ldg(&g_epack[j]);
            int cl = (int)ep;
            float v = __int_as_float((int)(ep >> 32));
            const __half2* rowp = S + (size_t)cl * 32 + l;
#pragma unroll
            for (int c = 0; c < C; c++) {
                float2 s = __half22float2(rowp[8 * c]);
                acc[c].x = fmaf(v, s.x, acc[c].x);
                acc[c].y = fmaf(v, s.y, acc[c].y);
            }
        }
#pragma unroll
        for (int c = 0; c < C; c++) {
            ys[c].x += fmaxf(acc[c].x, 0.f);
            ys[c].y += fmaxf(acc[c].y, 0.f);
        }
    }

    __shared__ float sm[256 * 8];
#pragma unroll
    for (int c = 0; c < C; c++) {
        sm[threadIdx.x * 8 + 2 * c + 0] = ys[c].x;
        sm[threadIdx.x * 8 + 2 * c + 1] = ys[c].y;
    }
    __syncthreads();
    if (threadIdx.x < 64) {
        int ll = threadIdx.x >> 3;
        int rem = threadIdx.x & 7;       // 2c+h
        float s = 0.f;
#pragma unroll 8
        for (int gg = 0; gg < 32; gg++) s += sm[(gg * 8 + ll) * 8 + rem];
        int c = rem >> 1, h = rem & 1;
        atomicAdd(&g_ysum[16 * c + 2 * ll + h], s);
    }
}

// ---------------------------------------------------------------------------
// head: y = ysum/N; z1 = relu(y@fc1W+fc1b); out = softmax(z1@fc2W+fc2b)
// ---------------------------------------------------------------------------
__global__ void head_kernel(const float* __restrict__ fc1W, const float* __restrict__ fc1b,
                            const float* __restrict__ fc2W, const float* __restrict__ fc2b,
                            float* __restrict__ out, float invN) {
    __shared__ float y[64];
    __shared__ float z1[32];
    __shared__ float z2[2];
    int t = threadIdx.x;
    y[t] = g_ysum[t] * invN;
    __syncthreads();
    if (t < 32) {
        float a = fc1b[t];
#pragma unroll
        for (int i = 0; i < 64; i++) a = fmaf(y[i], fc1W[i * 32 + t], a);
        z1[t] = fmaxf(a, 0.f);
    }
    __syncthreads();
    if (t < 2) {
        float a = fc2b[t];
#pragma unroll
        for (int i = 0; i < 32; i++) a = fmaf(z1[i], fc2W[i * 2 + t], a);
        z2[t] = a;
    }
    __syncthreads();
    if (t == 0) {
        float m = fmaxf(z2[0], z2[1]);
        float e0 = __expf(z2[0] - m), e1 = __expf(z2[1] - m);
        float inv = 1.f / (e0 + e1);
        out[0] = e0 * inv;
        out[1] = e1 * inv;
    }
}

// ---------------------------------------------------------------------------
extern "C" void kernel_launch(void* const* d_in, const int* in_sizes, int n_in,
                              void* d_out, int out_size) {
    const float* x    = (const float*)d_in[0];
    const int*   row  = (const int*)d_in[1];
    const int*   col  = (const int*)d_in[2];
    const float* ev   = (const float*)d_in[3];
    const float* W1   = (const float*)d_in[4];
    const float* b1   = (const float*)d_in[5];
    const float* W2   = (const float*)d_in[6];
    const float* b2   = (const float*)d_in[7];
    const float* W3   = (const float*)d_in[8];
    const float* b3   = (const float*)d_in[9];
    const float* fc1W = (const float*)d_in[10];
    const float* fc1b = (const float*)d_in[11];
    const float* fc2W = (const float*)d_in[12];
    const float* fc2b = (const float*)d_in[13];
    float* out = (float*)d_out;

    int N = in_sizes[0] / 256;   // NFEAT = 256
    int E = in_sizes[1];

    int nbN  = (N + 255) / 256;                 // 391
    int nbE  = (E + 255) / 256;                 // 6250
    int gG   = (N + 63) / 64;                   // 1563
    int cntB = (E + 1023) / 1024;               // 1563

    // ---- CSR build, gemm1 overlapped with count ----
    zero_cnt_kernel<<<nbN, 256>>>(N);
    gemm1_count_kernel<<<gG + cntB, 256>>>(x, W1, row, N, gG, E);
    scan1_kernel<<<nbN, 256>>>(N);
    scan2_kernel<<<1, 32>>>(nbN);
    scan3_kernel<<<nbN, 256>>>(N);
    fill_kernel<<<nbE, 256>>>(row, col, ev, E);

    // ---- Layer 1 spmm ----
    spmm_kernel<32><<<(N * 8 + 255) / 256, 256>>>(b1, N);
    // ---- Layer 2 ----
    gemm_kernel<32, 48, 32, true, false><<<gG, 256>>>(nullptr, W2, N);
    spmm_kernel<48><<<(N * 8 + 255) / 256, 256>>>(b2, N);
    // ---- Layer 3 (spmm fused with pool) ----
    gemm_kernel<48, 64, 48, true, false><<<gG, 256>>>(nullptr, W3, N);
    spmm3_pool_kernel<<<1184, 256>>>(b3, N);
    // ---- head ----
    head_kernel<<<1, 64>>>(fc1W, fc1b, fc2W, fc2b, out, 1.0f / (float)N);
}

// round 6
// speedup vs baseline: 1.4385x; 1.0311x over previous
#include <cuda_runtime.h>
#include <cuda_fp16.h>
#include <cstdint>

// ---------------------------------------------------------------------------
// GCN, round 6 (round-5 structure + alignment fix):
//  - CSR base via atomic cursor (no global scan chain; row order-free)
//  - SpMM: 4-lane groups/node, vector gathers (LF=12 uses 8B loads: ALIGNMENT),
//    2-edge unroll
//  - fp16 support matrix, fp32 accumulate; layer-3 SpMM fused with mean pool
// ---------------------------------------------------------------------------

#define MAXN 100000
#define MAXE 1600000

__device__ __align__(16) __half g_s16[(size_t)MAXN * 64];  // gemm out (fp16)
__device__ __align__(16) float  g_h[(size_t)MAXN * 64];    // spmm out (fp32)
__device__ float g_ysum[64];

__device__ int g_cnt[MAXN];
__device__ int g_ptr[MAXN];
__device__ int g_fill[MAXN];
__device__ int g_total;
__device__ __align__(16) long long g_epack[MAXE];   // (val<<32)|col

// ---- packed f32x2 helpers -------------------------------------------------
__device__ __forceinline__ unsigned long long splat2(float x) {
    unsigned long long r;
    asm("mov.b64 %0, {%1, %1};" : "=l"(r) : "f"(x));
    return r;
}
__device__ __forceinline__ void ffma2(unsigned long long& acc,
                                      unsigned long long w,
                                      unsigned long long x2) {
    asm("fma.rn.f32x2 %0, %1, %2, %0;" : "+l"(acc) : "l"(w), "l"(x2));
}
__device__ __forceinline__ float2 unpack2(unsigned long long v) {
    float2 f;
    asm("mov.b64 {%0, %1}, %2;" : "=f"(f.x), "=f"(f.y) : "l"(v));
    return f;
}

// ---------------------------------------------------------------------------
// Tiled GEMM body: g_s16[n,OUT] = act(X)[n,IN] @ W[IN,OUT]   (fp32 -> fp16)
// ---------------------------------------------------------------------------
template <int IN, int OUT, int KC, bool RELU_IN, bool FROM_PARAM>
__device__ __forceinline__ void gemm_body(const float* __restrict__ Xparam,
                                          const float* __restrict__ W,
                                          int n, int bid) {
    constexpr int OW = OUT / 4;
    constexpr int XS = KC + 1;
    __shared__ float Xs[64 * XS];
    __shared__ __align__(16) float Ws[KC * OUT];

    const float* __restrict__ X = FROM_PARAM ? Xparam : (const float*)g_h;

    const int node0 = bid * 64;
    const int t = threadIdx.x;
    const int node = t & 63;
    const int outg = t >> 6;
    const int gn = node0 + node;

    unsigned long long acc[OW / 2];
#pragma unroll
    for (int j = 0; j < OW / 2; j++) acc[j] = 0ull;

    for (int c = 0; c < IN / KC; c++) {
        for (int idx = t; idx < 64 * KC; idx += 256) {
            int nd = idx / KC, k = idx % KC;
            int g = node0 + nd;
            float v = (g < n) ? X[(size_t)g * IN + c * KC + k] : 0.f;
            if (RELU_IN) v = fmaxf(v, 0.f);
            Xs[nd * XS + k] = v;
        }
        for (int idx = t; idx < KC * OUT; idx += 256)
            Ws[idx] = W[c * KC * OUT + idx];
        __syncthreads();

        const float* xrow = &Xs[node * XS];
#pragma unroll 4
        for (int k = 0; k < KC; k++) {
            unsigned long long x2 = splat2(xrow[k]);
            const ulonglong2* wv = (const ulonglong2*)&Ws[k * OUT + outg * OW];
#pragma unroll
            for (int j = 0; j < OW / 4; j++) {
                ulonglong2 w = wv[j];
                ffma2(acc[2 * j + 0], w.x, x2);
                ffma2(acc[2 * j + 1], w.y, x2);
            }
        }
        __syncthreads();
    }

    if (gn < n) {
        __half2* dst = (__half2*)(g_s16 + (size_t)gn * OUT) + outg * (OW / 2);
#pragma unroll
        for (int j = 0; j < OW / 4; j++) {
            float2 a = unpack2(acc[2 * j + 0]);
            float2 b = unpack2(acc[2 * j + 1]);
            dst[2 * j + 0] = __floats2half2_rn(a.x, a.y);
            dst[2 * j + 1] = __floats2half2_rn(b.x, b.y);
        }
    }
}

// gemm1 fused with degree-count (independent; overlaps DRAM gemm w/ atomics)
__global__ void __launch_bounds__(256)
gemm1_count_kernel(const float* __restrict__ x, const float* __restrict__ W1,
                   const int* __restrict__ row, int n, int gG, int E) {
    if (blockIdx.x < gG) {
        gemm_body<256, 32, 64, false, true>(x, W1, n, blockIdx.x);
        return;
    }
    int e0 = ((blockIdx.x - gG) * 256 + threadIdx.x) * 4;
    if (e0 + 3 < E) {
        int4 r = *(const int4*)(row + e0);
        atomicAdd(&g_cnt[r.x], 1);
        atomicAdd(&g_cnt[r.y], 1);
        atomicAdd(&g_cnt[r.z], 1);
        atomicAdd(&g_cnt[r.w], 1);
    } else {
        for (int e = e0; e < E; e++) atomicAdd(&g_cnt[row[e]], 1);
    }
}

template <int IN, int OUT, int KC, bool RELU_IN, bool FROM_PARAM>
__global__ void __launch_bounds__(256)
gemm_kernel(const float* __restrict__ Xparam, const float* __restrict__ W, int n) {
    gemm_body<IN, OUT, KC, RELU_IN, FROM_PARAM>(Xparam, W, n, blockIdx.x);
}

// ---------------------------------------------------------------------------
// CSR build: zero, (count fused in gemm1), block-scan w/ atomic base, fill
// ---------------------------------------------------------------------------
__global__ void __launch_bounds__(256)
zero_cnt_kernel(int n) {
    int i = blockIdx.x * 256 + threadIdx.x;
    if (i < n) g_cnt[i] = 0;
    if (blockIdx.x == 0 && threadIdx.x == 0) g_total = 0;
    if (blockIdx.x == 0 && threadIdx.x < 64) g_ysum[threadIdx.x] = 0.f;
}

__global__ void __launch_bounds__(256)
scan_kernel(int n) {
    __shared__ int s[256];
    __shared__ int base;
    int t = threadIdx.x;
    int i = blockIdx.x * 256 + t;
    int v = (i < n) ? g_cnt[i] : 0;
    s[t] = v;
    __syncthreads();
#pragma unroll
    for (int off = 1; off < 256; off <<= 1) {
        int tmp = (t >= off) ? s[t - off] : 0;
        __syncthreads();
        s[t] += tmp;
        __syncthreads();
    }
    if (t == 255) base = atomicAdd(&g_total, s[255]);
    __syncthreads();
    if (i < n) {
        int p = base + s[t] - v;
        g_ptr[i] = p;
        g_fill[i] = p;
    }
}

__global__ void __launch_bounds__(256)
fill_kernel(const int* __restrict__ row, const int* __restrict__ col,
            const float* __restrict__ ev, int E) {
    int e0 = (blockIdx.x * 256 + threadIdx.x) * 2;
    if (e0 + 1 < E) {
        int2   r = *(const int2*)(row + e0);
        int2   c = *(const int2*)(col + e0);
        float2 v = *(const float2*)(ev + e0);
        int p0 = atomicAdd(&g_fill[r.x], 1);
        g_epack[p0] = ((long long)__float_as_int(v.x) << 32) | (unsigned int)c.x;
        int p1 = atomicAdd(&g_fill[r.y], 1);
        g_epack[p1] = ((long long)__float_as_int(v.y) << 32) | (unsigned int)c.y;
    } else {
        for (int e = e0; e < E; e++) {
            int p = atomicAdd(&g_fill[row[e]], 1);
            g_epack[p] = ((long long)__float_as_int(ev[e]) << 32) |
                         (unsigned int)col[e];
        }
    }
}

// ---------------------------------------------------------------------------
// Gather one lane's share of a support row (LF fp16 values) and fma.
// Alignment: LF=8 -> off 16l (16B ok); LF=12 -> off 24l (only 8B ok -> uint2);
//            LF=16 -> off 32l (16B ok).
// ---------------------------------------------------------------------------
template <int LF>
__device__ __forceinline__ void gather_fma(float* acc, const char* rowp, float v) {
    if (LF == 8) {                       // 16B: one uint4
        uint4 u = __ldg((const uint4*)rowp);
        const __half2* h = (const __half2*)&u;
#pragma unroll
        for (int i = 0; i < 4; i++) {
            float2 s = __half22float2(h[i]);
            acc[2 * i + 0] = fmaf(v, s.x, acc[2 * i + 0]);
            acc[2 * i + 1] = fmaf(v, s.y, acc[2 * i + 1]);
        }
    } else if (LF == 12) {               // 24B: three uint2 (8B-aligned for all lanes)
        uint2 u0 = __ldg((const uint2*)rowp);
        uint2 u1 = __ldg((const uint2*)(rowp + 8));
        uint2 u2 = __ldg((const uint2*)(rowp + 16));
        uint2 us[3] = {u0, u1, u2};
#pragma unroll
        for (int q = 0; q < 3; q++) {
            const __half2* h = (const __half2*)&us[q];
#pragma unroll
            for (int i = 0; i < 2; i++) {
                float2 s = __half22float2(h[i]);
                acc[q * 4 + 2 * i + 0] = fmaf(v, s.x, acc[q * 4 + 2 * i + 0]);
                acc[q * 4 + 2 * i + 1] = fmaf(v, s.y, acc[q * 4 + 2 * i + 1]);
            }
        }
    } else {                             // LF == 16, 32B: two uint4
        uint4 u0 = __ldg((const uint4*)rowp);
        uint4 u1 = __ldg((const uint4*)(rowp + 16));
        const __half2* h0 = (const __half2*)&u0;
        const __half2* h1 = (const __half2*)&u1;
#pragma unroll
        for (int i = 0; i < 4; i++) {
            float2 s = __half22float2(h0[i]);
            acc[2 * i + 0] = fmaf(v, s.x, acc[2 * i + 0]);
            acc[2 * i + 1] = fmaf(v, s.y, acc[2 * i + 1]);
        }
#pragma unroll
        for (int i = 0; i < 4; i++) {
            float2 s = __half22float2(h1[i]);
            acc[8 + 2 * i + 0] = fmaf(v, s.x, acc[8 + 2 * i + 0]);
            acc[8 + 2 * i + 1] = fmaf(v, s.y, acc[8 + 2 * i + 1]);
        }
    }
}

// ---------------------------------------------------------------------------
// SpMM (layers 1,2): 4-lane group per node; lane l owns cols [l*LF, (l+1)*LF).
// 2-edge unroll for MLP. g_h[node] = b + sum_j val_j * g_s16[col_j]
// ---------------------------------------------------------------------------
template <int F>
__global__ void __launch_bounds__(256)
spmm_kernel(const float* __restrict__ b, int n) {
    constexpr int LF = F / 4;
    int gid = (blockIdx.x * 256 + threadIdx.x) >> 2;
    int l = threadIdx.x & 3;
    if (gid >= n) return;

    float acc[LF];
#pragma unroll
    for (int i = 0; i < LF; i++) acc[i] = __ldg(&b[l * LF + i]);

    int j = g_ptr[gid];
    int end = j + g_cnt[gid];
    const char* __restrict__ S = (const char*)g_s16;
    const int laneoff = l * LF * 2;

    for (; j + 1 < end; j += 2) {
        long long ep0 = __ldg(&g_epack[j]);
        long long ep1 = __ldg(&g_epack[j + 1]);
        float v0 = __int_as_float((int)(ep0 >> 32));
        float v1 = __int_as_float((int)(ep1 >> 32));
        gather_fma<LF>(acc, S + (size_t)(int)ep0 * (F * 2) + laneoff, v0);
        gather_fma<LF>(acc, S + (size_t)(int)ep1 * (F * 2) + laneoff, v1);
    }
    if (j < end) {
        long long ep = __ldg(&g_epack[j]);
        float v = __int_as_float((int)(ep >> 32));
        gather_fma<LF>(acc, S + (size_t)(int)ep * (F * 2) + laneoff, v);
    }

    // F=32: l*8 floats = 32B-aligned; F=48: l*12 floats = 48B (16B-aligned). OK.
    float4* H = (float4*)(g_h + (size_t)gid * F + l * LF);
#pragma unroll
    for (int i = 0; i < LF / 4; i++)
        H[i] = make_float4(acc[4 * i], acc[4 * i + 1], acc[4 * i + 2], acc[4 * i + 3]);
}

// ---------------------------------------------------------------------------
// Layer-3 SpMM fused with mean pool (F=64): never materializes h3.
// ---------------------------------------------------------------------------
__global__ void __launch_bounds__(256)
spmm3_pool_kernel(const float* __restrict__ b, int n) {
    constexpr int LF = 16;
    int l = threadIdx.x & 3;
    int g = threadIdx.x >> 2;            // group in block, 0..63
    const char* __restrict__ S = (const char*)g_s16;
    const int laneoff = l * LF * 2;

    float bias[LF], ys[LF];
#pragma unroll
    for (int i = 0; i < LF; i++) {
        bias[i] = __ldg(&b[l * LF + i]);
        ys[i] = 0.f;
    }

    for (int node = blockIdx.x * 64 + g; node < n; node += gridDim.x * 64) {
        float acc[LF];
#pragma unroll
        for (int i = 0; i < LF; i++) acc[i] = bias[i];

        int j = g_ptr[node];
        int end = j + g_cnt[node];
        for (; j + 1 < end; j += 2) {
            long long ep0 = __ldg(&g_epack[j]);
            long long ep1 = __ldg(&g_epack[j + 1]);
            float v0 = __int_as_float((int)(ep0 >> 32));
            float v1 = __int_as_float((int)(ep1 >> 32));
            gather_fma<LF>(acc, S + (size_t)(int)ep0 * 128 + laneoff, v0);
            gather_fma<LF>(acc, S + (size_t)(int)ep1 * 128 + laneoff, v1);
        }
        if (j < end) {
            long long ep = __ldg(&g_epack[j]);
            float v = __int_as_float((int)(ep >> 32));
            gather_fma<LF>(acc, S + (size_t)(int)ep * 128 + laneoff, v);
        }
#pragma unroll
        for (int i = 0; i < LF; i++) ys[i] += fmaxf(acc[i], 0.f);
    }

    __shared__ float sm[256 * LF];
#pragma unroll
    for (int i = 0; i < LF; i++) sm[threadIdx.x * LF + i] = ys[i];
    __syncthreads();
    if (threadIdx.x < 64) {
        int ll = threadIdx.x >> 4;       // lane 0..3
        int slot = threadIdx.x & 15;
        float s = 0.f;
#pragma unroll 16
        for (int gg = 0; gg < 64; gg++) s += sm[(gg * 4 + ll) * LF + slot];
        atomicAdd(&g_ysum[ll * LF + slot], s);
    }
}

// ---------------------------------------------------------------------------
// head: y = ysum/N; z1 = relu(y@fc1W+fc1b); out = softmax(z1@fc2W+fc2b)
// ---------------------------------------------------------------------------
__global__ void head_kernel(const float* __restrict__ fc1W, const float* __restrict__ fc1b,
                            const float* __restrict__ fc2W, const float* __restrict__ fc2b,
                            float* __restrict__ out, float invN) {
    __shared__ float y[64];
    __shared__ float z1[32];
    __shared__ float z2[2];
    int t = threadIdx.x;
    y[t] = g_ysum[t] * invN;
    __syncthreads();
    if (t < 32) {
        float a = fc1b[t];
#pragma unroll
        for (int i = 0; i < 64; i++) a = fmaf(y[i], fc1W[i * 32 + t], a);
        z1[t] = fmaxf(a, 0.f);
    }
    __syncthreads();
    if (t < 2) {
        float a = fc2b[t];
#pragma unroll
        for (int i = 0; i < 32; i++) a = fmaf(z1[i], fc2W[i * 2 + t], a);
        z2[t] = a;
    }
    __syncthreads();
    if (t == 0) {
        float m = fmaxf(z2[0], z2[1]);
        float e0 = __expf(z2[0] - m), e1 = __expf(z2[1] - m);
        float inv = 1.f / (e0 + e1);
        out[0] = e0 * inv;
        out[1] = e1 * inv;
    }
}

// ---------------------------------------------------------------------------
extern "C" void kernel_launch(void* const* d_in, const int* in_sizes, int n_in,
                              void* d_out, int out_size) {
    const float* x    = (const float*)d_in[0];
    const int*   row  = (const int*)d_in[1];
    const int*   col  = (const int*)d_in[2];
    const float* ev   = (const float*)d_in[3];
    const float* W1   = (const float*)d_in[4];
    const float* b1   = (const float*)d_in[5];
    const float* W2   = (const float*)d_in[6];
    const float* b2   = (const float*)d_in[7];
    const float* W3   = (const float*)d_in[8];
    const float* b3   = (const float*)d_in[9];
    const float* fc1W = (const float*)d_in[10];
    const float* fc1b = (const float*)d_in[11];
    const float* fc2W = (const float*)d_in[12];
    const float* fc2b = (const float*)d_in[13];
    float* out = (float*)d_out;

    int N = in_sizes[0] / 256;   // NFEAT = 256
    int E = in_sizes[1];

    int nbN  = (N + 255) / 256;                 // 391
    int gG   = (N + 63) / 64;                   // 1563
    int cntB = (E + 1023) / 1024;               // 1563

    zero_cnt_kernel<<<nbN, 256>>>(N);
    gemm1_count_kernel<<<gG + cntB, 256>>>(x, W1, row, N, gG, E);
    scan_kernel<<<nbN, 256>>>(N);
    fill_kernel<<<(E / 2 + 255) / 256, 256>>>(row, col, ev, E);

    spmm_kernel<32><<<(N * 4 + 255) / 256, 256>>>(b1, N);
    gemm_kernel<32, 48, 32, true, false><<<gG, 256>>>(nullptr, W2, N);
    spmm_kernel<48><<<(N * 4 + 255) / 256, 256>>>(b2, N);
    gemm_kernel<48, 64, 48, true, false><<<gG, 256>>>(nullptr, W3, N);
    spmm3_pool_kernel<<<1184, 256>>>(b3, N);
    head_kernel<<<1, 64>>>(fc1W, fc1b, fc2W, fc2b, out, 1.0f / (float)N);
}

// round 8
// speedup vs baseline: 1.4959x; 1.0399x over previous
#include <cuda_runtime.h>
#include <cuda_fp16.h>
#include <cstdint>

// ---------------------------------------------------------------------------
// GCN, round 8 (= round 7 resubmitted after infra failure):
//  - fill fused into gemm1 launch (atomic-bound fill overlaps DRAM-bound gemm)
//  - SpMM: 8 lanes/node = 2 edge-lanes x 4 feature-lanes, 2-unroll (4 chains)
//  - fp16 support, fp32 accumulate; layer-3 SpMM fused with mean pool
// ---------------------------------------------------------------------------

#define MAXN 100000
#define MAXE 1600000

__device__ __align__(16) __half g_s16[(size_t)MAXN * 64];  // gemm out (fp16)
__device__ __align__(16) float  g_h[(size_t)MAXN * 64];    // spmm out (fp32)
__device__ float g_ysum[64];

__device__ int g_cnt[MAXN];
__device__ int g_ptr[MAXN];
__device__ int g_fill[MAXN];
__device__ int g_total;
__device__ __align__(16) long long g_epack[MAXE];   // (val<<32)|col

// ---- packed f32x2 helpers -------------------------------------------------
__device__ __forceinline__ unsigned long long splat2(float x) {
    unsigned long long r;
    asm("mov.b64 %0, {%1, %1};" : "=l"(r) : "f"(x));
    return r;
}
__device__ __forceinline__ void ffma2(unsigned long long& acc,
                                      unsigned long long w,
                                      unsigned long long x2) {
    asm("fma.rn.f32x2 %0, %1, %2, %0;" : "+l"(acc) : "l"(w), "l"(x2));
}
__device__ __forceinline__ float2 unpack2(unsigned long long v) {
    float2 f;
    asm("mov.b64 {%0, %1}, %2;" : "=f"(f.x), "=f"(f.y) : "l"(v));
    return f;
}

// ---------------------------------------------------------------------------
// Tiled GEMM body: g_s16[n,OUT] = act(X)[n,IN] @ W[IN,OUT]   (fp32 -> fp16)
// X tile staged with float4 global loads.
// ---------------------------------------------------------------------------
template <int IN, int OUT, int KC, bool RELU_IN, bool FROM_PARAM>
__device__ __forceinline__ void gemm_body(const float* __restrict__ Xparam,
                                          const float* __restrict__ W,
                                          int n, int bid) {
    constexpr int OW = OUT / 4;
    constexpr int XS = KC + 1;
    __shared__ float Xs[64 * XS];
    __shared__ __align__(16) float Ws[KC * OUT];

    const float* __restrict__ X = FROM_PARAM ? Xparam : (const float*)g_h;

    const int node0 = bid * 64;
    const int t = threadIdx.x;
    const int node = t & 63;
    const int outg = t >> 6;
    const int gn = node0 + node;

    unsigned long long acc[OW / 2];
#pragma unroll
    for (int j = 0; j < OW / 2; j++) acc[j] = 0ull;

    for (int c = 0; c < IN / KC; c++) {
        // X tile: float4 global loads, scalar smem stores (odd stride)
        constexpr int NV = 64 * KC / 4;
        for (int idx = t; idx < NV; idx += 256) {
            int nd = idx / (KC / 4), k4 = idx % (KC / 4);
            int g = node0 + nd;
            float4 v = make_float4(0.f, 0.f, 0.f, 0.f);
            if (g < n)
                v = *(const float4*)(X + (size_t)g * IN + c * KC + 4 * k4);
            if (RELU_IN) {
                v.x = fmaxf(v.x, 0.f); v.y = fmaxf(v.y, 0.f);
                v.z = fmaxf(v.z, 0.f); v.w = fmaxf(v.w, 0.f);
            }
            float* d = &Xs[nd * XS + 4 * k4];
            d[0] = v.x; d[1] = v.y; d[2] = v.z; d[3] = v.w;
        }
        for (int idx = t; idx < KC * OUT / 4; idx += 256)
            ((float4*)Ws)[idx] = ((const float4*)(W + c * KC * OUT))[idx];
        __syncthreads();

        const float* xrow = &Xs[node * XS];
#pragma unroll 4
        for (int k = 0; k < KC; k++) {
            unsigned long long x2 = splat2(xrow[k]);
            const ulonglong2* wv = (const ulonglong2*)&Ws[k * OUT + outg * OW];
#pragma unroll
            for (int j = 0; j < OW / 4; j++) {
                ulonglong2 w = wv[j];
                ffma2(acc[2 * j + 0], w.x, x2);
                ffma2(acc[2 * j + 1], w.y, x2);
            }
        }
        __syncthreads();
    }

    if (gn < n) {
        __half2* dst = (__half2*)(g_s16 + (size_t)gn * OUT) + outg * (OW / 2);
#pragma unroll
        for (int j = 0; j < OW / 4; j++) {
            float2 a = unpack2(acc[2 * j + 0]);
            float2 b = unpack2(acc[2 * j + 1]);
            dst[2 * j + 0] = __floats2half2_rn(a.x, a.y);
            dst[2 * j + 1] = __floats2half2_rn(b.x, b.y);
        }
    }
}

// count (standalone; needs zeroed g_cnt)
__global__ void __launch_bounds__(256)
count_kernel(const int* __restrict__ row, int E) {
    int e0 = (blockIdx.x * 256 + threadIdx.x) * 4;
    if (e0 + 3 < E) {
        int4 r = *(const int4*)(row + e0);
        atomicAdd(&g_cnt[r.x], 1);
        atomicAdd(&g_cnt[r.y], 1);
        atomicAdd(&g_cnt[r.z], 1);
        atomicAdd(&g_cnt[r.w], 1);
    } else {
        for (int e = e0; e < E; e++) atomicAdd(&g_cnt[row[e]], 1);
    }
}

// gemm1 fused with fill: DRAM-bound gemm overlaps L2-atomic-bound fill
__global__ void __launch_bounds__(256)
gemm1_fill_kernel(const float* __restrict__ x, const float* __restrict__ W1,
                  const int* __restrict__ row, const int* __restrict__ col,
                  const float* __restrict__ ev, int n, int gG, int E) {
    if (blockIdx.x < gG) {
        gemm_body<256, 32, 64, false, true>(x, W1, n, blockIdx.x);
        return;
    }
    int e0 = ((blockIdx.x - gG) * 256 + threadIdx.x) * 2;
    if (e0 + 1 < E) {
        int2   r = *(const int2*)(row + e0);
        int2   c = *(const int2*)(col + e0);
        float2 v = *(const float2*)(ev + e0);
        int p0 = atomicAdd(&g_fill[r.x], 1);
        g_epack[p0] = ((long long)__float_as_int(v.x) << 32) | (unsigned int)c.x;
        int p1 = atomicAdd(&g_fill[r.y], 1);
        g_epack[p1] = ((long long)__float_as_int(v.y) << 32) | (unsigned int)c.y;
    } else {
        for (int e = e0; e < E; e++) {
            int p = atomicAdd(&g_fill[row[e]], 1);
            g_epack[p] = ((long long)__float_as_int(ev[e]) << 32) |
                         (unsigned int)col[e];
        }
    }
}

template <int IN, int OUT, int KC, bool RELU_IN, bool FROM_PARAM>
__global__ void __launch_bounds__(256)
gemm_kernel(const float* __restrict__ Xparam, const float* __restrict__ W, int n) {
    gemm_body<IN, OUT, KC, RELU_IN, FROM_PARAM>(Xparam, W, n, blockIdx.x);
}

// ---------------------------------------------------------------------------
// CSR helpers
// ---------------------------------------------------------------------------
__global__ void __launch_bounds__(256)
zero_cnt_kernel(int n) {
    int i = blockIdx.x * 256 + threadIdx.x;
    if (i < n) g_cnt[i] = 0;
    if (blockIdx.x == 0 && threadIdx.x == 0) g_total = 0;
    if (blockIdx.x == 0 && threadIdx.x < 64) g_ysum[threadIdx.x] = 0.f;
}

__global__ void __launch_bounds__(256)
scan_kernel(int n) {
    __shared__ int s[256];
    __shared__ int base;
    int t = threadIdx.x;
    int i = blockIdx.x * 256 + t;
    int v = (i < n) ? g_cnt[i] : 0;
    s[t] = v;
    __syncthreads();
#pragma unroll
    for (int off = 1; off < 256; off <<= 1) {
        int tmp = (t >= off) ? s[t - off] : 0;
        __syncthreads();
        s[t] += tmp;
        __syncthreads();
    }
    if (t == 255) base = atomicAdd(&g_total, s[255]);
    __syncthreads();
    if (i < n) {
        int p = base + s[t] - v;
        g_ptr[i] = p;
        g_fill[i] = p;
    }
}

// ---------------------------------------------------------------------------
// Gather one feature-lane's share of a support row (LF fp16) and fma.
// LF=8: 16B uint4; LF=12: 3x uint2 (8B-aligned for all lanes); LF=16: 2x uint4.
// ---------------------------------------------------------------------------
template <int LF>
__device__ __forceinline__ void gather_fma(float* acc, const char* rowp, float v) {
    if (LF == 8) {
        uint4 u = __ldg((const uint4*)rowp);
        const __half2* h = (const __half2*)&u;
#pragma unroll
        for (int i = 0; i < 4; i++) {
            float2 s = __half22float2(h[i]);
            acc[2 * i + 0] = fmaf(v, s.x, acc[2 * i + 0]);
            acc[2 * i + 1] = fmaf(v, s.y, acc[2 * i + 1]);
        }
    } else if (LF == 12) {
        uint2 u0 = __ldg((const uint2*)rowp);
        uint2 u1 = __ldg((const uint2*)(rowp + 8));
        uint2 u2 = __ldg((const uint2*)(rowp + 16));
        uint2 us[3] = {u0, u1, u2};
#pragma unroll
        for (int q = 0; q < 3; q++) {
            const __half2* h = (const __half2*)&us[q];
#pragma unroll
            for (int i = 0; i < 2; i++) {
                float2 s = __half22float2(h[i]);
                acc[q * 4 + 2 * i + 0] = fmaf(v, s.x, acc[q * 4 + 2 * i + 0]);
                acc[q * 4 + 2 * i + 1] = fmaf(v, s.y, acc[q * 4 + 2 * i + 1]);
            }
        }
    } else {   // LF == 16
        uint4 u0 = __ldg((const uint4*)rowp);
        uint4 u1 = __ldg((const uint4*)(rowp + 16));
        const __half2* h0 = (const __half2*)&u0;
        const __half2* h1 = (const __half2*)&u1;
#pragma unroll
        for (int i = 0; i < 4; i++) {
            float2 s = __half22float2(h0[i]);
            acc[2 * i + 0] = fmaf(v, s.x, acc[2 * i + 0]);
            acc[2 * i + 1] = fmaf(v, s.y, acc[2 * i + 1]);
        }
#pragma unroll
        for (int i = 0; i < 4; i++) {
            float2 s = __half22float2(h1[i]);
            acc[8 + 2 * i + 0] = fmaf(v, s.x, acc[8 + 2 * i + 0]);
            acc[8 + 2 * i + 1] = fmaf(v, s.y, acc[8 + 2 * i + 1]);
        }
    }
}

// ---------------------------------------------------------------------------
// SpMM (layers 1,2): 8 lanes/node = 2 edge-lanes x 4 feature-lanes.
// Edge-lane el takes edges ptr+el, +2, +4...; 2-unroll -> 4 chains in flight.
// Combine edge-lanes with one shfl_xor(1) per node. NO early return (shuffle).
// ---------------------------------------------------------------------------
template <int F>
__global__ void __launch_bounds__(256)
spmm_kernel(const float* __restrict__ b, int n) {
    constexpr int LF = F / 4;
    int gid = (blockIdx.x * 256 + threadIdx.x) >> 3;
    int l = threadIdx.x & 7;
    int el = l & 1, fl = l >> 1;
    bool active = (gid < n);

    float acc[LF];
#pragma unroll
    for (int i = 0; i < LF; i++)
        acc[i] = (el == 0) ? __ldg(&b[fl * LF + i]) : 0.f;

    const char* __restrict__ S = (const char*)g_s16;
    const int laneoff = fl * LF * 2;

    if (active) {
        int p = g_ptr[gid];
        int end = p + g_cnt[gid];
        int j = p + el;
        for (; j + 2 < end; j += 4) {
            long long ep0 = __ldg(&g_epack[j]);
            long long ep1 = __ldg(&g_epack[j + 2]);
            float v0 = __int_as_float((int)(ep0 >> 32));
            float v1 = __int_as_float((int)(ep1 >> 32));
            gather_fma<LF>(acc, S + (size_t)(int)ep0 * (F * 2) + laneoff, v0);
            gather_fma<LF>(acc, S + (size_t)(int)ep1 * (F * 2) + laneoff, v1);
        }
        if (j < end) {
            long long ep = __ldg(&g_epack[j]);
            float v = __int_as_float((int)(ep >> 32));
            gather_fma<LF>(acc, S + (size_t)(int)ep * (F * 2) + laneoff, v);
        }
    }

#pragma unroll
    for (int i = 0; i < LF; i++)
        acc[i] += __shfl_xor_sync(0xffffffffu, acc[i], 1);

    if (active && el == 0) {
        float4* H = (float4*)(g_h + (size_t)gid * F + fl * LF);
#pragma unroll
        for (int i = 0; i < LF / 4; i++)
            H[i] = make_float4(acc[4 * i], acc[4 * i + 1],
                               acc[4 * i + 2], acc[4 * i + 3]);
    }
}

// ---------------------------------------------------------------------------
// Layer-3 SpMM fused with mean pool (F=64): 8 lanes/node, 32 groups/block.
// ---------------------------------------------------------------------------
__global__ void __launch_bounds__(256)
spmm3_pool_kernel(const float* __restrict__ b, int n) {
    constexpr int LF = 16;
    int l = threadIdx.x & 7;
    int el = l & 1, fl = l >> 1;
    int g = threadIdx.x >> 3;            // group in block, 0..31
    const char* __restrict__ S = (const char*)g_s16;
    const int laneoff = fl * LF * 2;

    float bias[LF], ys[LF];
#pragma unroll
    for (int i = 0; i < LF; i++) {
        bias[i] = (el == 0) ? __ldg(&b[fl * LF + i]) : 0.f;
        ys[i] = 0.f;
    }

    for (int node = blockIdx.x * 32 + g; node < n; node += gridDim.x * 32) {
        float acc[LF];
#pragma unroll
        for (int i = 0; i < LF; i++) acc[i] = bias[i];

        int p = g_ptr[node];
        int end = p + g_cnt[node];
        int j = p + el;
        for (; j + 2 < end; j += 4) {
            long long ep0 = __ldg(&g_epack[j]);
            long long ep1 = __ldg(&g_epack[j + 2]);
            float v0 = __int_as_float((int)(ep0 >> 32));
            float v1 = __int_as_float((int)(ep1 >> 32));
            gather_fma<LF>(acc, S + (size_t)(int)ep0 * 128 + laneoff, v0);
            gather_fma<LF>(acc, S + (size_t)(int)ep1 * 128 + laneoff, v1);
        }
        if (j < end) {
            long long ep = __ldg(&g_epack[j]);
            float v = __int_as_float((int)(ep >> 32));
            gather_fma<LF>(acc, S + (size_t)(int)ep * 128 + laneoff, v);
        }
        // combine edge lanes, relu, accumulate into ys (el==0 lanes hold sum)
#pragma unroll
        for (int i = 0; i < LF; i++) {
            float s = acc[i] + __shfl_xor_sync(0xffffffffu, acc[i], 1);
            ys[i] += fmaxf(s, 0.f);
        }
    }

    // ys valid on el==0 lanes: 4 feature-lanes per group, 32 groups
    __shared__ float sm[128 * LF];
    if (el == 0) {
#pragma unroll
        for (int i = 0; i < LF; i++) sm[(g * 4 + fl) * LF + i] = ys[i];
    }
    __syncthreads();
    if (threadIdx.x < 64) {
        int ll = threadIdx.x >> 4;       // feature lane 0..3
        int slot = threadIdx.x & 15;
        float s = 0.f;
#pragma unroll 16
        for (int gg = 0; gg < 32; gg++) s += sm[(gg * 4 + ll) * LF + slot];
        atomicAdd(&g_ysum[ll * LF + slot], s);
    }
}

// ---------------------------------------------------------------------------
// head
// ---------------------------------------------------------------------------
__global__ void head_kernel(const float* __restrict__ fc1W, const float* __restrict__ fc1b,
                            const float* __restrict__ fc2W, const float* __restrict__ fc2b,
                            float* __restrict__ out, float invN) {
    __shared__ float y[64];
    __shared__ float z1[32];
    __shared__ float z2[2];
    int t = threadIdx.x;
    y[t] = g_ysum[t] * invN;
    __syncthreads();
    if (t < 32) {
        float a = fc1b[t];
#pragma unroll
        for (int i = 0; i < 64; i++) a = fmaf(y[i], fc1W[i * 32 + t], a);
        z1[t] = fmaxf(a, 0.f);
    }
    __syncthreads();
    if (t < 2) {
        float a = fc2b[t];
#pragma unroll
        for (int i = 0; i < 32; i++) a = fmaf(z1[i], fc2W[i * 2 + t], a);
        z2[t] = a;
    }
    __syncthreads();
    if (t == 0) {
        float m = fmaxf(z2[0], z2[1]);
        float e0 = __expf(z2[0] - m), e1 = __expf(z2[1] - m);
        float inv = 1.f / (e0 + e1);
        out[0] = e0 * inv;
        out[1] = e1 * inv;
    }
}

// ---------------------------------------------------------------------------
extern "C" void kernel_launch(void* const* d_in, const int* in_sizes, int n_in,
                              void* d_out, int out_size) {
    const float* x    = (const float*)d_in[0];
    const int*   row  = (const int*)d_in[1];
    const int*   col  = (const int*)d_in[2];
    const float* ev   = (const float*)d_in[3];
    const float* W1   = (const float*)d_in[4];
    const float* b1   = (const float*)d_in[5];
    const float* W2   = (const float*)d_in[6];
    const float* b2   = (const float*)d_in[7];
    const float* W3   = (const float*)d_in[8];
    const float* b3   = (const float*)d_in[9];
    const float* fc1W = (const float*)d_in[10];
    const float* fc1b = (const float*)d_in[11];
    const float* fc2W = (const float*)d_in[12];
    const float* fc2b = (const float*)d_in[13];
    float* out = (float*)d_out;

    int N = in_sizes[0] / 256;   // NFEAT = 256
    int E = in_sizes[1];

    int nbN   = (N + 255) / 256;                 // 391
    int gG    = (N + 63) / 64;                   // 1563
    int cntB  = (E + 1023) / 1024;               // 1563
    int fillB = (E / 2 + 255) / 256;             // 3125
    int spB   = (N * 8 + 255) / 256;             // 3125

    zero_cnt_kernel<<<nbN, 256>>>(N);
    count_kernel<<<cntB, 256>>>(row, E);
    scan_kernel<<<nbN, 256>>>(N);
    gemm1_fill_kernel<<<gG + fillB, 256>>>(x, W1, row, col, ev, N, gG, E);

    spmm_kernel<32><<<spB, 256>>>(b1, N);
    gemm_kernel<32, 48, 32, true, false><<<gG, 256>>>(nullptr, W2, N);
    spmm_kernel<48><<<spB, 256>>>(b2, N);
    gemm_kernel<48, 64, 48, true, false><<<gG, 256>>>(nullptr, W3, N);
    spmm3_pool_kernel<<<1184, 256>>>(b3, N);
    head_kernel<<<1, 64>>>(fc1W, fc1b, fc2W, fc2b, out, 1.0f / (float)N);
}

// round 9
// speedup vs baseline: 1.5407x; 1.0300x over previous
#include <cuda_runtime.h>
#include <cuda_fp16.h>
#include <cstdint>

// ---------------------------------------------------------------------------
// GCN, round 9:
//  - gemm1 moved to tensor cores (mma.sync m16n8k8 tf32), fill still fused
//  - gemm2/3 stay on f32x2 (convert next round if layouts verify)
//  - SpMM: 8 lanes/node, fp16 gathers, fp32 accum; layer-3 fused w/ mean pool
// ---------------------------------------------------------------------------

#define MAXN 100000
#define MAXE 1600000

__device__ __align__(16) __half g_s16[(size_t)MAXN * 64];  // gemm out (fp16)
__device__ __align__(16) float  g_h[(size_t)MAXN * 64];    // spmm out (fp32)
__device__ float g_ysum[64];

__device__ int g_cnt[MAXN];
__device__ int g_ptr[MAXN];
__device__ int g_fill[MAXN];
__device__ int g_total;
__device__ __align__(16) long long g_epack[MAXE];   // (val<<32)|col

// ---- packed f32x2 helpers -------------------------------------------------
__device__ __forceinline__ unsigned long long splat2(float x) {
    unsigned long long r;
    asm("mov.b64 %0, {%1, %1};" : "=l"(r) : "f"(x));
    return r;
}
__device__ __forceinline__ void ffma2(unsigned long long& acc,
                                      unsigned long long w,
                                      unsigned long long x2) {
    asm("fma.rn.f32x2 %0, %1, %2, %0;" : "+l"(acc) : "l"(w), "l"(x2));
}
__device__ __forceinline__ float2 unpack2(unsigned long long v) {
    float2 f;
    asm("mov.b64 {%0, %1}, %2;" : "=f"(f.x), "=f"(f.y) : "l"(v));
    return f;
}

// ---- tf32 mma helpers -----------------------------------------------------
__device__ __forceinline__ uint32_t f2tf32(float f) {
    uint32_t o;
    asm("cvt.rna.tf32.f32 %0, %1;" : "=r"(o) : "f"(f));
    return o;
}
__device__ __forceinline__ void mma_tf32(float* c, uint32_t a0, uint32_t a1,
                                         uint32_t a2, uint32_t a3,
                                         uint32_t b0, uint32_t b1) {
    asm("mma.sync.aligned.m16n8k8.row.col.f32.tf32.tf32.f32 "
        "{%0,%1,%2,%3}, {%4,%5,%6,%7}, {%8,%9}, {%0,%1,%2,%3};"
        : "+f"(c[0]), "+f"(c[1]), "+f"(c[2]), "+f"(c[3])
        : "r"(a0), "r"(a1), "r"(a2), "r"(a3), "r"(b0), "r"(b1));
}

// ---------------------------------------------------------------------------
// gemm1 (tensor core): g_s16[n,32] = X[n,256] @ W[256,32]
// Block = 256 thr, 64-node tile. 8 warps = 4 (m16) x 2 (n16).
// K staged in KC=64 chunks, cvt to tf32 at staging.
// Fragment layout (m16n8k8.tf32, g=lane>>2, tg=lane&3):
//   A: a0=(g,tg) a1=(g+8,tg) a2=(g,tg+4) a3=(g+8,tg+4)   [row-major 16x8]
//   B: b0=B[k=tg][n=g] b1=B[k=tg+4][n=g]                  [k8 x n8]
//   C: c0=(g,2tg) c1=(g,2tg+1) c2=(g+8,2tg) c3=(g+8,2tg+1)
// ---------------------------------------------------------------------------
__device__ __forceinline__ void gemm1_tc_body(const float* __restrict__ X,
                                              const float* __restrict__ W,
                                              int n, int bid) {
    constexpr int IN = 256, OUT = 32, KC = 64;
    constexpr int XS = KC + 1;     // 65
    constexpr int WS = OUT + 1;    // 33
    __shared__ uint32_t Xs[64 * XS];
    __shared__ uint32_t Ws[KC * WS];

    const int t = threadIdx.x;
    const int lane = t & 31;
    const int w = t >> 5;
    const int mrow = (w & 3) * 16;      // 0,16,32,48
    const int n0 = (w >> 2) * 16;       // 0,16
    const int g = lane >> 2;
    const int tg = lane & 3;
    const int node0 = bid * 64;

    float c0[4] = {0.f, 0.f, 0.f, 0.f};
    float c1[4] = {0.f, 0.f, 0.f, 0.f};

    for (int ch = 0; ch < IN / KC; ch++) {
        // stage X tile (float4 loads, tf32 scalar stores)
        for (int idx = t; idx < 64 * KC / 4; idx += 256) {
            int nd = idx / (KC / 4), k4 = idx % (KC / 4);
            int gn = node0 + nd;
            float4 v = make_float4(0.f, 0.f, 0.f, 0.f);
            if (gn < n)
                v = *(const float4*)(X + (size_t)gn * IN + ch * KC + 4 * k4);
            uint32_t* d = &Xs[nd * XS + 4 * k4];
            d[0] = f2tf32(v.x); d[1] = f2tf32(v.y);
            d[2] = f2tf32(v.z); d[3] = f2tf32(v.w);
        }
        // stage W chunk [KC][OUT]
        for (int idx = t; idx < KC * OUT / 4; idx += 256) {
            float4 v = *(const float4*)(W + ch * KC * OUT + 4 * idx);
            int kk = (4 * idx) / OUT, nn = (4 * idx) % OUT;
            uint32_t* d = &Ws[kk * WS + nn];
            d[0] = f2tf32(v.x); d[1] = f2tf32(v.y);
            d[2] = f2tf32(v.z); d[3] = f2tf32(v.w);
        }
        __syncthreads();

#pragma unroll
        for (int k = 0; k < KC; k += 8) {
            uint32_t a0 = Xs[(mrow + g) * XS + k + tg];
            uint32_t a1 = Xs[(mrow + g + 8) * XS + k + tg];
            uint32_t a2 = Xs[(mrow + g) * XS + k + tg + 4];
            uint32_t a3 = Xs[(mrow + g + 8) * XS + k + tg + 4];
            uint32_t b0 = Ws[(k + tg) * WS + n0 + g];
            uint32_t b1 = Ws[(k + tg + 4) * WS + n0 + g];
            mma_tf32(c0, a0, a1, a2, a3, b0, b1);
            uint32_t b2 = Ws[(k + tg) * WS + n0 + 8 + g];
            uint32_t b3 = Ws[(k + tg + 4) * WS + n0 + 8 + g];
            mma_tf32(c1, a0, a1, a2, a3, b2, b3);
        }
        __syncthreads();
    }

    int r0 = node0 + mrow + g;
    int r1 = r0 + 8;
    if (r0 < n) {
        *(__half2*)(g_s16 + (size_t)r0 * OUT + n0 + 2 * tg) =
            __floats2half2_rn(c0[0], c0[1]);
        *(__half2*)(g_s16 + (size_t)r0 * OUT + n0 + 8 + 2 * tg) =
            __floats2half2_rn(c1[0], c1[1]);
    }
    if (r1 < n) {
        *(__half2*)(g_s16 + (size_t)r1 * OUT + n0 + 2 * tg) =
            __floats2half2_rn(c0[2], c0[3]);
        *(__half2*)(g_s16 + (size_t)r1 * OUT + n0 + 8 + 2 * tg) =
            __floats2half2_rn(c1[2], c1[3]);
    }
}

// ---------------------------------------------------------------------------
// Tiled GEMM body (f32x2 path, layers 2/3): g_s16[n,OUT] = relu(g_h)[n,IN]@W
// ---------------------------------------------------------------------------
template <int IN, int OUT, int KC, bool RELU_IN, bool FROM_PARAM>
__device__ __forceinline__ void gemm_body(const float* __restrict__ Xparam,
                                          const float* __restrict__ W,
                                          int n, int bid) {
    constexpr int OW = OUT / 4;
    constexpr int XS = KC + 1;
    __shared__ float Xs[64 * XS];
    __shared__ __align__(16) float Ws[KC * OUT];

    const float* __restrict__ X = FROM_PARAM ? Xparam : (const float*)g_h;

    const int node0 = bid * 64;
    const int t = threadIdx.x;
    const int node = t & 63;
    const int outg = t >> 6;
    const int gn = node0 + node;

    unsigned long long acc[OW / 2];
#pragma unroll
    for (int j = 0; j < OW / 2; j++) acc[j] = 0ull;

    for (int c = 0; c < IN / KC; c++) {
        constexpr int NV = 64 * KC / 4;
        for (int idx = t; idx < NV; idx += 256) {
            int nd = idx / (KC / 4), k4 = idx % (KC / 4);
            int g = node0 + nd;
            float4 v = make_float4(0.f, 0.f, 0.f, 0.f);
            if (g < n)
                v = *(const float4*)(X + (size_t)g * IN + c * KC + 4 * k4);
            if (RELU_IN) {
                v.x = fmaxf(v.x, 0.f); v.y = fmaxf(v.y, 0.f);
                v.z = fmaxf(v.z, 0.f); v.w = fmaxf(v.w, 0.f);
            }
            float* d = &Xs[nd * XS + 4 * k4];
            d[0] = v.x; d[1] = v.y; d[2] = v.z; d[3] = v.w;
        }
        for (int idx = t; idx < KC * OUT / 4; idx += 256)
            ((float4*)Ws)[idx] = ((const float4*)(W + c * KC * OUT))[idx];
        __syncthreads();

        const float* xrow = &Xs[node * XS];
#pragma unroll 4
        for (int k = 0; k < KC; k++) {
            unsigned long long x2 = splat2(xrow[k]);
            const ulonglong2* wv = (const ulonglong2*)&Ws[k * OUT + outg * OW];
#pragma unroll
            for (int j = 0; j < OW / 4; j++) {
                ulonglong2 w = wv[j];
                ffma2(acc[2 * j + 0], w.x, x2);
                ffma2(acc[2 * j + 1], w.y, x2);
            }
        }
        __syncthreads();
    }

    if (gn < n) {
        __half2* dst = (__half2*)(g_s16 + (size_t)gn * OUT) + outg * (OW / 2);
#pragma unroll
        for (int j = 0; j < OW / 4; j++) {
            float2 a = unpack2(acc[2 * j + 0]);
            float2 b = unpack2(acc[2 * j + 1]);
            dst[2 * j + 0] = __floats2half2_rn(a.x, a.y);
            dst[2 * j + 1] = __floats2half2_rn(b.x, b.y);
        }
    }
}

// count (standalone; needs zeroed g_cnt)
__global__ void __launch_bounds__(256)
count_kernel(const int* __restrict__ row, int E) {
    int e0 = (blockIdx.x * 256 + threadIdx.x) * 4;
    if (e0 + 3 < E) {
        int4 r = *(const int4*)(row + e0);
        atomicAdd(&g_cnt[r.x], 1);
        atomicAdd(&g_cnt[r.y], 1);
        atomicAdd(&g_cnt[r.z], 1);
        atomicAdd(&g_cnt[r.w], 1);
    } else {
        for (int e = e0; e < E; e++) atomicAdd(&g_cnt[row[e]], 1);
    }
}

// gemm1 (tensor core) fused with fill
__global__ void __launch_bounds__(256)
gemm1_fill_kernel(const float* __restrict__ x, const float* __restrict__ W1,
                  const int* __restrict__ row, const int* __restrict__ col,
                  const float* __restrict__ ev, int n, int gG, int E) {
    if (blockIdx.x < gG) {
        gemm1_tc_body(x, W1, n, blockIdx.x);
        return;
    }
    int e0 = ((blockIdx.x - gG) * 256 + threadIdx.x) * 2;
    if (e0 + 1 < E) {
        int2   r = *(const int2*)(row + e0);
        int2   c = *(const int2*)(col + e0);
        float2 v = *(const float2*)(ev + e0);
        int p0 = atomicAdd(&g_fill[r.x], 1);
        g_epack[p0] = ((long long)__float_as_int(v.x) << 32) | (unsigned int)c.x;
        int p1 = atomicAdd(&g_fill[r.y], 1);
        g_epack[p1] = ((long long)__float_as_int(v.y) << 32) | (unsigned int)c.y;
    } else {
        for (int e = e0; e < E; e++) {
            int p = atomicAdd(&g_fill[row[e]], 1);
            g_epack[p] = ((long long)__float_as_int(ev[e]) << 32) |
                         (unsigned int)col[e];
        }
    }
}

template <int IN, int OUT, int KC, bool RELU_IN, bool FROM_PARAM>
__global__ void __launch_bounds__(256)
gemm_kernel(const float* __restrict__ Xparam, const float* __restrict__ W, int n) {
    gemm_body<IN, OUT, KC, RELU_IN, FROM_PARAM>(Xparam, W, n, blockIdx.x);
}

// ---------------------------------------------------------------------------
// CSR helpers
// ---------------------------------------------------------------------------
__global__ void __launch_bounds__(256)
zero_cnt_kernel(int n) {
    int i = blockIdx.x * 256 + threadIdx.x;
    if (i < n) g_cnt[i] = 0;
    if (blockIdx.x == 0 && threadIdx.x == 0) g_total = 0;
    if (blockIdx.x == 0 && threadIdx.x < 64) g_ysum[threadIdx.x] = 0.f;
}

__global__ void __launch_bounds__(256)
scan_kernel(int n) {
    __shared__ int s[256];
    __shared__ int base;
    int t = threadIdx.x;
    int i = blockIdx.x * 256 + t;
    int v = (i < n) ? g_cnt[i] : 0;
    s[t] = v;
    __syncthreads();
#pragma unroll
    for (int off = 1; off < 256; off <<= 1) {
        int tmp = (t >= off) ? s[t - off] : 0;
        __syncthreads();
        s[t] += tmp;
        __syncthreads();
    }
    if (t == 255) base = atomicAdd(&g_total, s[255]);
    __syncthreads();
    if (i < n) {
        int p = base + s[t] - v;
        g_ptr[i] = p;
        g_fill[i] = p;
    }
}

// ---------------------------------------------------------------------------
// Gather one feature-lane's share of a support row (LF fp16) and fma.
// ---------------------------------------------------------------------------
template <int LF>
__device__ __forceinline__ void gather_fma(float* acc, const char* rowp, float v) {
    if (LF == 8) {
        uint4 u = __ldg((const uint4*)rowp);
        const __half2* h = (const __half2*)&u;
#pragma unroll
        for (int i = 0; i < 4; i++) {
            float2 s = __half22float2(h[i]);
            acc[2 * i + 0] = fmaf(v, s.x, acc[2 * i + 0]);
            acc[2 * i + 1] = fmaf(v, s.y, acc[2 * i + 1]);
        }
    } else if (LF == 12) {
        uint2 u0 = __ldg((const uint2*)rowp);
        uint2 u1 = __ldg((const uint2*)(rowp + 8));
        uint2 u2 = __ldg((const uint2*)(rowp + 16));
        uint2 us[3] = {u0, u1, u2};
#pragma unroll
        for (int q = 0; q < 3; q++) {
            const __half2* h = (const __half2*)&us[q];
#pragma unroll
            for (int i = 0; i < 2; i++) {
                float2 s = __half22float2(h[i]);
                acc[q * 4 + 2 * i + 0] = fmaf(v, s.x, acc[q * 4 + 2 * i + 0]);
                acc[q * 4 + 2 * i + 1] = fmaf(v, s.y, acc[q * 4 + 2 * i + 1]);
            }
        }
    } else {   // LF == 16
        uint4 u0 = __ldg((const uint4*)rowp);
        uint4 u1 = __ldg((const uint4*)(rowp + 16));
        const __half2* h0 = (const __half2*)&u0;
        const __half2* h1 = (const __half2*)&u1;
#pragma unroll
        for (int i = 0; i < 4; i++) {
            float2 s = __half22float2(h0[i]);
            acc[2 * i + 0] = fmaf(v, s.x, acc[2 * i + 0]);
            acc[2 * i + 1] = fmaf(v, s.y, acc[2 * i + 1]);
        }
#pragma unroll
        for (int i = 0; i < 4; i++) {
            float2 s = __half22float2(h1[i]);
            acc[8 + 2 * i + 0] = fmaf(v, s.x, acc[8 + 2 * i + 0]);
            acc[8 + 2 * i + 1] = fmaf(v, s.y, acc[8 + 2 * i + 1]);
        }
    }
}

// ---------------------------------------------------------------------------
// SpMM (layers 1,2): 8 lanes/node = 2 edge-lanes x 4 feature-lanes.
// ---------------------------------------------------------------------------
template <int F>
__global__ void __launch_bounds__(256)
spmm_kernel(const float* __restrict__ b, int n) {
    constexpr int LF = F / 4;
    int gid = (blockIdx.x * 256 + threadIdx.x) >> 3;
    int l = threadIdx.x & 7;
    int el = l & 1, fl = l >> 1;
    bool active = (gid < n);

    float acc[LF];
#pragma unroll
    for (int i = 0; i < LF; i++)
        acc[i] = (el == 0) ? __ldg(&b[fl * LF + i]) : 0.f;

    const char* __restrict__ S = (const char*)g_s16;
    const int laneoff = fl * LF * 2;

    if (active) {
        int p = g_ptr[gid];
        int end = p + g_cnt[gid];
        int j = p + el;
        for (; j + 2 < end; j += 4) {
            long long ep0 = __ldg(&g_epack[j]);
            long long ep1 = __ldg(&g_epack[j + 2]);
            float v0 = __int_as_float((int)(ep0 >> 32));
            float v1 = __int_as_float((int)(ep1 >> 32));
            gather_fma<LF>(acc, S + (size_t)(int)ep0 * (F * 2) + laneoff, v0);
            gather_fma<LF>(acc, S + (size_t)(int)ep1 * (F * 2) + laneoff, v1);
        }
        if (j < end) {
            long long ep = __ldg(&g_epack[j]);
            float v = __int_as_float((int)(ep >> 32));
            gather_fma<LF>(acc, S + (size_t)(int)ep * (F * 2) + laneoff, v);
        }
    }

#pragma unroll
    for (int i = 0; i < LF; i++)
        acc[i] += __shfl_xor_sync(0xffffffffu, acc[i], 1);

    if (active && el == 0) {
        float4* H = (float4*)(g_h + (size_t)gid * F + fl * LF);
#pragma unroll
        for (int i = 0; i < LF / 4; i++)
            H[i] = make_float4(acc[4 * i], acc[4 * i + 1],
                               acc[4 * i + 2], acc[4 * i + 3]);
    }
}

// ---------------------------------------------------------------------------
// Layer-3 SpMM fused with mean pool (F=64): 8 lanes/node, 32 groups/block.
// ---------------------------------------------------------------------------
__global__ void __launch_bounds__(256)
spmm3_pool_kernel(const float* __restrict__ b, int n) {
    constexpr int LF = 16;
    int l = threadIdx.x & 7;
    int el = l & 1, fl = l >> 1;
    int g = threadIdx.x >> 3;            // group in block, 0..31
    const char* __restrict__ S = (const char*)g_s16;
    const int laneoff = fl * LF * 2;

    float bias[LF], ys[LF];
#pragma unroll
    for (int i = 0; i < LF; i++) {
        bias[i] = (el == 0) ? __ldg(&b[fl * LF + i]) : 0.f;
        ys[i] = 0.f;
    }

    for (int node = blockIdx.x * 32 + g; node < n; node += gridDim.x * 32) {
        float acc[LF];
#pragma unroll
        for (int i = 0; i < LF; i++) acc[i] = bias[i];

        int p = g_ptr[node];
        int end = p + g_cnt[node];
        int j = p + el;
        for (; j + 2 < end; j += 4) {
            long long ep0 = __ldg(&g_epack[j]);
            long long ep1 = __ldg(&g_epack[j + 2]);
            float v0 = __int_as_float((int)(ep0 >> 32));
            float v1 = __int_as_float((int)(ep1 >> 32));
            gather_fma<LF>(acc, S + (size_t)(int)ep0 * 128 + laneoff, v0);
            gather_fma<LF>(acc, S + (size_t)(int)ep1 * 128 + laneoff, v1);
        }
        if (j < end) {
            long long ep = __ldg(&g_epack[j]);
            float v = __int_as_float((int)(ep >> 32));
            gather_fma<LF>(acc, S + (size_t)(int)ep * 128 + laneoff, v);
        }
#pragma unroll
        for (int i = 0; i < LF; i++) {
            float s = acc[i] + __shfl_xor_sync(0xffffffffu, acc[i], 1);
            ys[i] += fmaxf(s, 0.f);
        }
    }

    __shared__ float sm[128 * LF];
    if (el == 0) {
#pragma unroll
        for (int i = 0; i < LF; i++) sm[(g * 4 + fl) * LF + i] = ys[i];
    }
    __syncthreads();
    if (threadIdx.x < 64) {
        int ll = threadIdx.x >> 4;       // feature lane 0..3
        int slot = threadIdx.x & 15;
        float s = 0.f;
#pragma unroll 16
        for (int gg = 0; gg < 32; gg++) s += sm[(gg * 4 + ll) * LF + slot];
        atomicAdd(&g_ysum[ll * LF + slot], s);
    }
}

// ---------------------------------------------------------------------------
// head
// ---------------------------------------------------------------------------
__global__ void head_kernel(const float* __restrict__ fc1W, const float* __restrict__ fc1b,
                            const float* __restrict__ fc2W, const float* __restrict__ fc2b,
                            float* __restrict__ out, float invN) {
    __shared__ float y[64];
    __shared__ float z1[32];
    __shared__ float z2[2];
    int t = threadIdx.x;
    y[t] = g_ysum[t] * invN;
    __syncthreads();
    if (t < 32) {
        float a = fc1b[t];
#pragma unroll
        for (int i = 0; i < 64; i++) a = fmaf(y[i], fc1W[i * 32 + t], a);
        z1[t] = fmaxf(a, 0.f);
    }
    __syncthreads();
    if (t < 2) {
        float a = fc2b[t];
#pragma unroll
        for (int i = 0; i < 32; i++) a = fmaf(z1[i], fc2W[i * 2 + t], a);
        z2[t] = a;
    }
    __syncthreads();
    if (t == 0) {
        float m = fmaxf(z2[0], z2[1]);
        float e0 = __expf(z2[0] - m), e1 = __expf(z2[1] - m);
        float inv = 1.f / (e0 + e1);
        out[0] = e0 * inv;
        out[1] = e1 * inv;
    }
}

// ---------------------------------------------------------------------------
extern "C" void kernel_launch(void* const* d_in, const int* in_sizes, int n_in,
                              void* d_out, int out_size) {
    const float* x    = (const float*)d_in[0];
    const int*   row  = (const int*)d_in[1];
    const int*   col  = (const int*)d_in[2];
    const float* ev   = (const float*)d_in[3];
    const float* W1   = (const float*)d_in[4];
    const float* b1   = (const float*)d_in[5];
    const float* W2   = (const float*)d_in[6];
    const float* b2   = (const float*)d_in[7];
    const float* W3   = (const float*)d_in[8];
    const float* b3   = (const float*)d_in[9];
    const float* fc1W = (const float*)d_in[10];
    const float* fc1b = (const float*)d_in[11];
    const float* fc2W = (const float*)d_in[12];
    const float* fc2b = (const float*)d_in[13];
    float* out = (float*)d_out;

    int N = in_sizes[0] / 256;   // NFEAT = 256
    int E = in_sizes[1];

    int nbN   = (N + 255) / 256;                 // 391
    int gG    = (N + 63) / 64;                   // 1563
    int cntB  = (E + 1023) / 1024;               // 1563
    int fillB = (E / 2 + 255) / 256;             // 3125
    int spB   = (N * 8 + 255) / 256;             // 3125

    zero_cnt_kernel<<<nbN, 256>>>(N);
    count_kernel<<<cntB, 256>>>(row, E);
    scan_kernel<<<nbN, 256>>>(N);
    gemm1_fill_kernel<<<gG + fillB, 256>>>(x, W1, row, col, ev, N, gG, E);

    spmm_kernel<32><<<spB, 256>>>(b1, N);
    gemm_kernel<32, 48, 32, true, false><<<gG, 256>>>(nullptr, W2, N);
    spmm_kernel<48><<<spB, 256>>>(b2, N);
    gemm_kernel<48, 64, 48, true, false><<<gG, 256>>>(nullptr, W3, N);
    spmm3_pool_kernel<<<1184, 256>>>(b3, N);
    head_kernel<<<1, 64>>>(fc1W, fc1b, fc2W, fc2b, out, 1.0f / (float)N);
}

// round 10
// speedup vs baseline: 1.8493x; 1.2003x over previous
#include <cuda_runtime.h>
#include <cuda_fp16.h>
#include <cstdint>

// ---------------------------------------------------------------------------
// GCN, round 10:
//  - gemm1: fp16 tensor cores (m16n8k16) fed by ldmatrix.x4 -> LDS traffic /8
//  - fill still fused into gemm1 launch; gemm2/3 stay f32x2
//  - SpMM: 8 lanes/node, fp16 gathers, fp32 accum; layer-3 fused w/ mean pool
// ---------------------------------------------------------------------------

#define MAXN 100000
#define MAXE 1600000

__device__ __align__(16) __half g_s16[(size_t)MAXN * 64];  // gemm out (fp16)
__device__ __align__(16) float  g_h[(size_t)MAXN * 64];    // spmm out (fp32)
__device__ float g_ysum[64];

__device__ int g_cnt[MAXN];
__device__ int g_ptr[MAXN];
__device__ int g_fill[MAXN];
__device__ int g_total;
__device__ __align__(16) long long g_epack[MAXE];   // (val<<32)|col

// ---- packed f32x2 helpers -------------------------------------------------
__device__ __forceinline__ unsigned long long splat2(float x) {
    unsigned long long r;
    asm("mov.b64 %0, {%1, %1};" : "=l"(r) : "f"(x));
    return r;
}
__device__ __forceinline__ void ffma2(unsigned long long& acc,
                                      unsigned long long w,
                                      unsigned long long x2) {
    asm("fma.rn.f32x2 %0, %1, %2, %0;" : "+l"(acc) : "l"(w), "l"(x2));
}
__device__ __forceinline__ float2 unpack2(unsigned long long v) {
    float2 f;
    asm("mov.b64 {%0, %1}, %2;" : "=f"(f.x), "=f"(f.y) : "l"(v));
    return f;
}

// ---- fp16 mma helpers -----------------------------------------------------
__device__ __forceinline__ uint32_t smem_u32(const void* p) {
    return (uint32_t)__cvta_generic_to_shared(p);
}
__device__ __forceinline__ void ldmatrix_x4(uint32_t& r0, uint32_t& r1,
                                            uint32_t& r2, uint32_t& r3,
                                            uint32_t addr) {
    asm volatile("ldmatrix.sync.aligned.m8n8.x4.shared.b16 {%0,%1,%2,%3}, [%4];"
                 : "=r"(r0), "=r"(r1), "=r"(r2), "=r"(r3) : "r"(addr));
}
__device__ __forceinline__ void mma_f16(float* c, uint32_t a0, uint32_t a1,
                                        uint32_t a2, uint32_t a3,
                                        uint32_t b0, uint32_t b1) {
    asm("mma.sync.aligned.m16n8k16.row.col.f32.f16.f16.f32 "
        "{%0,%1,%2,%3}, {%4,%5,%6,%7}, {%8,%9}, {%0,%1,%2,%3};"
        : "+f"(c[0]), "+f"(c[1]), "+f"(c[2]), "+f"(c[3])
        : "r"(a0), "r"(a1), "r"(a2), "r"(a3), "r"(b0), "r"(b1));
}

// ---------------------------------------------------------------------------
// gemm1 (fp16 TC): g_s16[n,32] = X[n,256] @ W[256,32]
// Block = 256 thr, 64-node tile. 8 warps = 4 (m16) x 2 (n16).
// X staged fp16 [64][XS], W staged transposed Wt[n][k] fp16.
// ldmatrix.x4 row map: row = base + (lane&15), col(bytes) = ((lane>>4)<<3)*2.
//   A tiles -> a0..a3 = (rlo,klo)(rhi,klo)(rlo,khi)(rhi,khi)  [matches mma A]
//   B tiles on Wt -> r0=b0(nlo) r1=b0(nhi) r2=b1(nlo) r3=b1(nhi)
// C: c0=(g,2tg) c1=(g,2tg+1) c2=(g+8,2tg) c3=(g+8,2tg+1)
// ---------------------------------------------------------------------------
__device__ __forceinline__ void gemm1_tc_body(const float* __restrict__ X,
                                              const float* __restrict__ W,
                                              int n, int bid) {
    constexpr int IN = 256, OUT = 32, KC = 64;
    constexpr int XS = KC + 8;   // 72 halves = 144B stride (16B-aligned, ldmatrix conflict-free)
    __shared__ __align__(16) __half Xs[64 * XS];
    __shared__ __align__(16) __half Wt[32 * XS];

    const int t = threadIdx.x;
    const int lane = t & 31;
    const int w = t >> 5;
    const int mrow = (w & 3) << 4;      // 0,16,32,48
    const int n0 = (w >> 2) << 4;       // 0,16
    const int g = lane >> 2;
    const int tg = lane & 3;
    const int node0 = bid * 64;

    const int lrow = lane & 15;
    const int lcolh = (lane >> 4) << 3;  // 0 or 8 halves

    float c0[4] = {0.f, 0.f, 0.f, 0.f};
    float c1[4] = {0.f, 0.f, 0.f, 0.f};

    for (int ch = 0; ch < IN / KC; ch++) {
        // stage X tile (float4 loads -> half2 stores)
        for (int idx = t; idx < 64 * KC / 4; idx += 256) {
            int nd = idx / (KC / 4), k4 = idx % (KC / 4);
            int gn = node0 + nd;
            float4 v = make_float4(0.f, 0.f, 0.f, 0.f);
            if (gn < n)
                v = *(const float4*)(X + (size_t)gn * IN + ch * KC + 4 * k4);
            __half2* d = (__half2*)&Xs[nd * XS + 4 * k4];
            d[0] = __floats2half2_rn(v.x, v.y);
            d[1] = __floats2half2_rn(v.z, v.w);
        }
        // stage W chunk transposed: Wt[nn][k]
        for (int idx = t; idx < KC * OUT; idx += 256) {
            int k = idx >> 5, nn = idx & 31;
            Wt[nn * XS + k] = __float2half(W[(ch * KC + k) * OUT + nn]);
        }
        __syncthreads();

        uint32_t aaddr = smem_u32(&Xs[(mrow + lrow) * XS + lcolh]);
        uint32_t baddr = smem_u32(&Wt[(n0 + lrow) * XS + lcolh]);
#pragma unroll
        for (int k16 = 0; k16 < KC; k16 += 16) {
            uint32_t a0, a1, a2, a3, b0, b1, b2, b3;
            ldmatrix_x4(a0, a1, a2, a3, aaddr + k16 * 2);
            ldmatrix_x4(b0, b1, b2, b3, baddr + k16 * 2);
            mma_f16(c0, a0, a1, a2, a3, b0, b2);
            mma_f16(c1, a0, a1, a2, a3, b1, b3);
        }
        __syncthreads();
    }

    int r0 = node0 + mrow + g;
    int r1 = r0 + 8;
    if (r0 < n) {
        *(__half2*)(g_s16 + (size_t)r0 * OUT + n0 + 2 * tg) =
            __floats2half2_rn(c0[0], c0[1]);
        *(__half2*)(g_s16 + (size_t)r0 * OUT + n0 + 8 + 2 * tg) =
            __floats2half2_rn(c1[0], c1[1]);
    }
    if (r1 < n) {
        *(__half2*)(g_s16 + (size_t)r1 * OUT + n0 + 2 * tg) =
            __floats2half2_rn(c0[2], c0[3]);
        *(__half2*)(g_s16 + (size_t)r1 * OUT + n0 + 8 + 2 * tg) =
            __floats2half2_rn(c1[2], c1[3]);
    }
}

// ---------------------------------------------------------------------------
// Tiled GEMM body (f32x2 path, layers 2/3): g_s16[n,OUT] = relu(g_h)[n,IN]@W
// ---------------------------------------------------------------------------
template <int IN, int OUT, int KC, bool RELU_IN, bool FROM_PARAM>
__device__ __forceinline__ void gemm_body(const float* __restrict__ Xparam,
                                          const float* __restrict__ W,
                                          int n, int bid) {
    constexpr int OW = OUT / 4;
    constexpr int XS = KC + 1;
    __shared__ float Xs[64 * XS];
    __shared__ __align__(16) float Ws[KC * OUT];

    const float* __restrict__ X = FROM_PARAM ? Xparam : (const float*)g_h;

    const int node0 = bid * 64;
    const int t = threadIdx.x;
    const int node = t & 63;
    const int outg = t >> 6;
    const int gn = node0 + node;

    unsigned long long acc[OW / 2];
#pragma unroll
    for (int j = 0; j < OW / 2; j++) acc[j] = 0ull;

    for (int c = 0; c < IN / KC; c++) {
        constexpr int NV = 64 * KC / 4;
        for (int idx = t; idx < NV; idx += 256) {
            int nd = idx / (KC / 4), k4 = idx % (KC / 4);
            int g = node0 + nd;
            float4 v = make_float4(0.f, 0.f, 0.f, 0.f);
            if (g < n)
                v = *(const float4*)(X + (size_t)g * IN + c * KC + 4 * k4);
            if (RELU_IN) {
                v.x = fmaxf(v.x, 0.f); v.y = fmaxf(v.y, 0.f);
                v.z = fmaxf(v.z, 0.f); v.w = fmaxf(v.w, 0.f);
            }
            float* d = &Xs[nd * XS + 4 * k4];
            d[0] = v.x; d[1] = v.y; d[2] = v.z; d[3] = v.w;
        }
        for (int idx = t; idx < KC * OUT / 4; idx += 256)
            ((float4*)Ws)[idx] = ((const float4*)(W + c * KC * OUT))[idx];
        __syncthreads();

        const float* xrow = &Xs[node * XS];
#pragma unroll 4
        for (int k = 0; k < KC; k++) {
            unsigned long long x2 = splat2(xrow[k]);
            const ulonglong2* wv = (const ulonglong2*)&Ws[k * OUT + outg * OW];
#pragma unroll
            for (int j = 0; j < OW / 4; j++) {
                ulonglong2 w = wv[j];
                ffma2(acc[2 * j + 0], w.x, x2);
                ffma2(acc[2 * j + 1], w.y, x2);
            }
        }
        __syncthreads();
    }

    if (gn < n) {
        __half2* dst = (__half2*)(g_s16 + (size_t)gn * OUT) + outg * (OW / 2);
#pragma unroll
        for (int j = 0; j < OW / 4; j++) {
            float2 a = unpack2(acc[2 * j + 0]);
            float2 b = unpack2(acc[2 * j + 1]);
            dst[2 * j + 0] = __floats2half2_rn(a.x, a.y);
            dst[2 * j + 1] = __floats2half2_rn(b.x, b.y);
        }
    }
}

// count (standalone; needs zeroed g_cnt)
__global__ void __launch_bounds__(256)
count_kernel(const int* __restrict__ row, int E) {
    int e0 = (blockIdx.x * 256 + threadIdx.x) * 4;
    if (e0 + 3 < E) {
        int4 r = *(const int4*)(row + e0);
        atomicAdd(&g_cnt[r.x], 1);
        atomicAdd(&g_cnt[r.y], 1);
        atomicAdd(&g_cnt[r.z], 1);
        atomicAdd(&g_cnt[r.w], 1);
    } else {
        for (int e = e0; e < E; e++) atomicAdd(&g_cnt[row[e]], 1);
    }
}

// gemm1 (fp16 TC) fused with fill
__global__ void __launch_bounds__(256)
gemm1_fill_kernel(const float* __restrict__ x, const float* __restrict__ W1,
                  const int* __restrict__ row, const int* __restrict__ col,
                  const float* __restrict__ ev, int n, int gG, int E) {
    if (blockIdx.x < gG) {
        gemm1_tc_body(x, W1, n, blockIdx.x);
        return;
    }
    int e0 = ((blockIdx.x - gG) * 256 + threadIdx.x) * 2;
    if (e0 + 1 < E) {
        int2   r = *(const int2*)(row + e0);
        int2   c = *(const int2*)(col + e0);
        float2 v = *(const float2*)(ev + e0);
        int p0 = atomicAdd(&g_fill[r.x], 1);
        g_epack[p0] = ((long long)__float_as_int(v.x) << 32) | (unsigned int)c.x;
        int p1 = atomicAdd(&g_fill[r.y], 1);
        g_epack[p1] = ((long long)__float_as_int(v.y) << 32) | (unsigned int)c.y;
    } else {
        for (int e = e0; e < E; e++) {
            int p = atomicAdd(&g_fill[row[e]], 1);
            g_epack[p] = ((long long)__float_as_int(ev[e]) << 32) |
                         (unsigned int)col[e];
        }
    }
}

template <int IN, int OUT, int KC, bool RELU_IN, bool FROM_PARAM>
__global__ void __launch_bounds__(256)
gemm_kernel(const float* __restrict__ Xparam, const float* __restrict__ W, int n) {
    gemm_body<IN, OUT, KC, RELU_IN, FROM_PARAM>(Xparam, W, n, blockIdx.x);
}

// ---------------------------------------------------------------------------
// CSR helpers
// ---------------------------------------------------------------------------
__global__ void __launch_bounds__(256)
zero_cnt_kernel(int n) {
    int i = blockIdx.x * 256 + threadIdx.x;
    if (i < n) g_cnt[i] = 0;
    if (blockIdx.x == 0 && threadIdx.x == 0) g_total = 0;
    if (blockIdx.x == 0 && threadIdx.x < 64) g_ysum[threadIdx.x] = 0.f;
}

__global__ void __launch_bounds__(256)
scan_kernel(int n) {
    __shared__ int s[256];
    __shared__ int base;
    int t = threadIdx.x;
    int i = blockIdx.x * 256 + t;
    int v = (i < n) ? g_cnt[i] : 0;
    s[t] = v;
    __syncthreads();
#pragma unroll
    for (int off = 1; off < 256; off <<= 1) {
        int tmp = (t >= off) ? s[t - off] : 0;
        __syncthreads();
        s[t] += tmp;
        __syncthreads();
    }
    if (t == 255) base = atomicAdd(&g_total, s[255]);
    __syncthreads();
    if (i < n) {
        int p = base + s[t] - v;
        g_ptr[i] = p;
        g_fill[i] = p;
    }
}

// ---------------------------------------------------------------------------
// Gather one feature-lane's share of a support row (LF fp16) and fma.
// ---------------------------------------------------------------------------
template <int LF>
__device__ __forceinline__ void gather_fma(float* acc, const char* rowp, float v) {
    if (LF == 8) {
        uint4 u = __ldg((const uint4*)rowp);
        const __half2* h = (const __half2*)&u;
#pragma unroll
        for (int i = 0; i < 4; i++) {
            float2 s = __half22float2(h[i]);
            acc[2 * i + 0] = fmaf(v, s.x, acc[2 * i + 0]);
            acc[2 * i + 1] = fmaf(v, s.y, acc[2 * i + 1]);
        }
    } else if (LF == 12) {
        uint2 u0 = __ldg((const uint2*)rowp);
        uint2 u1 = __ldg((const uint2*)(rowp + 8));
        uint2 u2 = __ldg((const uint2*)(rowp + 16));
        uint2 us[3] = {u0, u1, u2};
#pragma unroll
        for (int q = 0; q < 3; q++) {
            const __half2* h = (const __half2*)&us[q];
#pragma unroll
            for (int i = 0; i < 2; i++) {
                float2 s = __half22float2(h[i]);
                acc[q * 4 + 2 * i + 0] = fmaf(v, s.x, acc[q * 4 + 2 * i + 0]);
                acc[q * 4 + 2 * i + 1] = fmaf(v, s.y, acc[q * 4 + 2 * i + 1]);
            }
        }
    } else {   // LF == 16
        uint4 u0 = __ldg((const uint4*)rowp);
        uint4 u1 = __ldg((const uint4*)(rowp + 16));
        const __half2* h0 = (const __half2*)&u0;
        const __half2* h1 = (const __half2*)&u1;
#pragma unroll
        for (int i = 0; i < 4; i++) {
            float2 s = __half22float2(h0[i]);
            acc[2 * i + 0] = fmaf(v, s.x, acc[2 * i + 0]);
            acc[2 * i + 1] = fmaf(v, s.y, acc[2 * i + 1]);
        }
#pragma unroll
        for (int i = 0; i < 4; i++) {
            float2 s = __half22float2(h1[i]);
            acc[8 + 2 * i + 0] = fmaf(v, s.x, acc[8 + 2 * i + 0]);
            acc[8 + 2 * i + 1] = fmaf(v, s.y, acc[8 + 2 * i + 1]);
        }
    }
}

// ---------------------------------------------------------------------------
// SpMM (layers 1,2): 8 lanes/node = 2 edge-lanes x 4 feature-lanes.
// ---------------------------------------------------------------------------
template <int F>
__global__ void __launch_bounds__(256)
spmm_kernel(const float* __restrict__ b, int n) {
    constexpr int LF = F / 4;
    int gid = (blockIdx.x * 256 + threadIdx.x) >> 3;
    int l = threadIdx.x & 7;
    int el = l & 1, fl = l >> 1;
    bool active = (gid < n);

    float acc[LF];
#pragma unroll
    for (int i = 0; i < LF; i++)
        acc[i] = (el == 0) ? __ldg(&b[fl * LF + i]) : 0.f;

    const char* __restrict__ S = (const char*)g_s16;
    const int laneoff = fl * LF * 2;

    if (active) {
        int p = g_ptr[gid];
        int end = p + g_cnt[gid];
        int j = p + el;
        for (; j + 2 < end; j += 4) {
            long long ep0 = __ldg(&g_epack[j]);
            long long ep1 = __ldg(&g_epack[j + 2]);
            float v0 = __int_as_float((int)(ep0 >> 32));
            float v1 = __int_as_float((int)(ep1 >> 32));
            gather_fma<LF>(acc, S + (size_t)(int)ep0 * (F * 2) + laneoff, v0);
            gather_fma<LF>(acc, S + (size_t)(int)ep1 * (F * 2) + laneoff, v1);
        }
        if (j < end) {
            long long ep = __ldg(&g_epack[j]);
            float v = __int_as_float((int)(ep >> 32));
            gather_fma<LF>(acc, S + (size_t)(int)ep * (F * 2) + laneoff, v);
        }
    }

#pragma unroll
    for (int i = 0; i < LF; i++)
        acc[i] += __shfl_xor_sync(0xffffffffu, acc[i], 1);

    if (active && el == 0) {
        float4* H = (float4*)(g_h + (size_t)gid * F + fl * LF);
#pragma unroll
        for (int i = 0; i < LF / 4; i++)
            H[i] = make_float4(acc[4 * i], acc[4 * i + 1],
                               acc[4 * i + 2], acc[4 * i + 3]);
    }
}

// ---------------------------------------------------------------------------
// Layer-3 SpMM fused with mean pool (F=64): 8 lanes/node, 32 groups/block.
// ---------------------------------------------------------------------------
__global__ void __launch_bounds__(256)
spmm3_pool_kernel(const float* __restrict__ b, int n) {
    constexpr int LF = 16;
    int l = threadIdx.x & 7;
    int el = l & 1, fl = l >> 1;
    int g = threadIdx.x >> 3;            // group in block, 0..31
    const char* __restrict__ S = (const char*)g_s16;
    const int laneoff = fl * LF * 2;

    float bias[LF], ys[LF];
#pragma unroll
    for (int i = 0; i < LF; i++) {
        bias[i] = (el == 0) ? __ldg(&b[fl * LF + i]) : 0.f;
        ys[i] = 0.f;
    }

    for (int node = blockIdx.x * 32 + g; node < n; node += gridDim.x * 32) {
        float acc[LF];
#pragma unroll
        for (int i = 0; i < LF; i++) acc[i] = bias[i];

        int p = g_ptr[node];
        int end = p + g_cnt[node];
        int j = p + el;
        for (; j + 2 < end; j += 4) {
            long long ep0 = __ldg(&g_epack[j]);
            long long ep1 = __ldg(&g_epack[j + 2]);
            float v0 = __int_as_float((int)(ep0 >> 32));
            float v1 = __int_as_float((int)(ep1 >> 32));
            gather_fma<LF>(acc, S + (size_t)(int)ep0 * 128 + laneoff, v0);
            gather_fma<LF>(acc, S + (size_t)(int)ep1 * 128 + laneoff, v1);
        }
        if (j < end) {
            long long ep = __ldg(&g_epack[j]);
            float v = __int_as_float((int)(ep >> 32));
            gather_fma<LF>(acc, S + (size_t)(int)ep * 128 + laneoff, v);
        }
#pragma unroll
        for (int i = 0; i < LF; i++) {
            float s = acc[i] + __shfl_xor_sync(0xffffffffu, acc[i], 1);
            ys[i] += fmaxf(s, 0.f);
        }
    }

    __shared__ float sm[128 * LF];
    if (el == 0) {
#pragma unroll
        for (int i = 0; i < LF; i++) sm[(g * 4 + fl) * LF + i] = ys[i];
    }
    __syncthreads();
    if (threadIdx.x < 64) {
        int ll = threadIdx.x >> 4;       // feature lane 0..3
        int slot = threadIdx.x & 15;
        float s = 0.f;
#pragma unroll 16
        for (int gg = 0; gg < 32; gg++) s += sm[(gg * 4 + ll) * LF + slot];
        atomicAdd(&g_ysum[ll * LF + slot], s);
    }
}

// ---------------------------------------------------------------------------
// head
// ---------------------------------------------------------------------------
__global__ void head_kernel(const float* __restrict__ fc1W, const float* __restrict__ fc1b,
                            const float* __restrict__ fc2W, const float* __restrict__ fc2b,
                            float* __restrict__ out, float invN) {
    __shared__ float y[64];
    __shared__ float z1[32];
    __shared__ float z2[2];
    int t = threadIdx.x;
    y[t] = g_ysum[t] * invN;
    __syncthreads();
    if (t < 32) {
        float a = fc1b[t];
#pragma unroll
        for (int i = 0; i < 64; i++) a = fmaf(y[i], fc1W[i * 32 + t], a);
        z1[t] = fmaxf(a, 0.f);
    }
    __syncthreads();
    if (t < 2) {
        float a = fc2b[t];
#pragma unroll
        for (int i = 0; i < 32; i++) a = fmaf(z1[i], fc2W[i * 2 + t], a);
        z2[t] = a;
    }
    __syncthreads();
    if (t == 0) {
        float m = fmaxf(z2[0], z2[1]);
        float e0 = __expf(z2[0] - m), e1 = __expf(z2[1] - m);
        float inv = 1.f / (e0 + e1);
        out[0] = e0 * inv;
        out[1] = e1 * inv;
    }
}

// ---------------------------------------------------------------------------
extern "C" void kernel_launch(void* const* d_in, const int* in_sizes, int n_in,
                              void* d_out, int out_size) {
    const float* x    = (const float*)d_in[0];
    const int*   row  = (const int*)d_in[1];
    const int*   col  = (const int*)d_in[2];
    const float* ev   = (const float*)d_in[3];
    const float* W1   = (const float*)d_in[4];
    const float* b1   = (const float*)d_in[5];
    const float* W2   = (const float*)d_in[6];
    const float* b2   = (const float*)d_in[7];
    const float* W3   = (const float*)d_in[8];
    const float* b3   = (const float*)d_in[9];
    const float* fc1W = (const float*)d_in[10];
    const float* fc1b = (const float*)d_in[11];
    const float* fc2W = (const float*)d_in[12];
    const float* fc2b = (const float*)d_in[13];
    float* out = (float*)d_out;

    int N = in_sizes[0] / 256;   // NFEAT = 256
    int E = in_sizes[1];

    int nbN   = (N + 255) / 256;                 // 391
    int gG    = (N + 63) / 64;                   // 1563
    int cntB  = (E + 1023) / 1024;               // 1563
    int fillB = (E / 2 + 255) / 256;             // 3125
    int spB   = (N * 8 + 255) / 256;             // 3125

    zero_cnt_kernel<<<nbN, 256>>>(N);
    count_kernel<<<cntB, 256>>>(row, E);
    scan_kernel<<<nbN, 256>>>(N);
    gemm1_fill_kernel<<<gG + fillB, 256>>>(x, W1, row, col, ev, N, gG, E);

    spmm_kernel<32><<<spB, 256>>>(b1, N);
    gemm_kernel<32, 48, 32, true, false><<<gG, 256>>>(nullptr, W2, N);
    spmm_kernel<48><<<spB, 256>>>(b2, N);
    gemm_kernel<48, 64, 48, true, false><<<gG, 256>>>(nullptr, W3, N);
    spmm3_pool_kernel<<<1184, 256>>>(b3, N);
    head_kernel<<<1, 64>>>(fc1W, fc1b, fc2W, fc2b, out, 1.0f / (float)N);
}

// round 11
// speedup vs baseline: 2.0548x; 1.1111x over previous
#include <cuda_runtime.h>
#include <cuda_fp16.h>
#include <cstdint>

// ---------------------------------------------------------------------------
// GCN, round 11:
//  - ALL three gemms on fp16 tensor cores (m16n8k16 + ldmatrix.x4)
//  - CSR prep: 2 kernels (scan self-zeroes cnt; g_fill doubles as row end)
//  - SpMM: 8 lanes/node, 4-deep gather unroll; layer-3 fused w/ mean pool
// ---------------------------------------------------------------------------

#define MAXN 100000
#define MAXE 1600000

__device__ __align__(16) __half g_s16[(size_t)MAXN * 64];  // gemm out (fp16)
__device__ __align__(16) float  g_h[(size_t)MAXN * 64];    // spmm out (fp32)
__device__ float g_ysum[64];

__device__ int g_cnt[MAXN];     // zeroed by scan after read (static-0 at load)
__device__ int g_ptr[MAXN];     // row start
__device__ int g_fill[MAXN];    // fill cursor; == row end after fill
__device__ int g_total;         // zeroed inside gemm1_fill (static-0 at load)
__device__ __align__(16) long long g_epack[MAXE];   // (val<<32)|col

// ---- fp16 mma helpers -----------------------------------------------------
__device__ __forceinline__ uint32_t smem_u32(const void* p) {
    return (uint32_t)__cvta_generic_to_shared(p);
}
__device__ __forceinline__ void ldmatrix_x4(uint32_t& r0, uint32_t& r1,
                                            uint32_t& r2, uint32_t& r3,
                                            uint32_t addr) {
    asm volatile("ldmatrix.sync.aligned.m8n8.x4.shared.b16 {%0,%1,%2,%3}, [%4];"
                 : "=r"(r0), "=r"(r1), "=r"(r2), "=r"(r3) : "r"(addr));
}
__device__ __forceinline__ void mma_f16(float* c, uint32_t a0, uint32_t a1,
                                        uint32_t a2, uint32_t a3,
                                        uint32_t b0, uint32_t b1) {
    asm("mma.sync.aligned.m16n8k16.row.col.f32.f16.f16.f32 "
        "{%0,%1,%2,%3}, {%4,%5,%6,%7}, {%8,%9}, {%0,%1,%2,%3};"
        : "+f"(c[0]), "+f"(c[1]), "+f"(c[2]), "+f"(c[3])
        : "r"(a0), "r"(a1), "r"(a2), "r"(a3), "r"(b0), "r"(b1));
}

// ---------------------------------------------------------------------------
// gemm1 (fp16 TC): g_s16[n,32] = X[n,256] @ W[256,32]
// Block = 256 thr, 64-node tile. 8 warps = 4 (m16) x 2 (n16). KC=128.
// ---------------------------------------------------------------------------
__device__ __forceinline__ void gemm1_tc_body(const float* __restrict__ X,
                                              const float* __restrict__ W,
                                              int n, int bid) {
    constexpr int IN = 256, OUT = 32, KC = 128;
    constexpr int XS = KC + 8;   // 136 halves = 272B stride (16B-mult, conflict-free)
    __shared__ __align__(16) __half Xs[64 * XS];
    __shared__ __align__(16) __half Wt[32 * XS];

    const int t = threadIdx.x;
    const int lane = t & 31;
    const int w = t >> 5;
    const int mrow = (w & 3) << 4;      // 0,16,32,48
    const int n0 = (w >> 2) << 4;       // 0,16
    const int g = lane >> 2;
    const int tg = lane & 3;
    const int node0 = bid * 64;

    const int lrow = lane & 15;
    const int lcolh = (lane >> 4) << 3;  // 0 or 8 halves

    float c0[4] = {0.f, 0.f, 0.f, 0.f};
    float c1[4] = {0.f, 0.f, 0.f, 0.f};

    for (int ch = 0; ch < IN / KC; ch++) {
        for (int idx = t; idx < 64 * KC / 4; idx += 256) {
            int nd = idx / (KC / 4), k4 = idx % (KC / 4);
            int gn = node0 + nd;
            float4 v = make_float4(0.f, 0.f, 0.f, 0.f);
            if (gn < n)
                v = *(const float4*)(X + (size_t)gn * IN + ch * KC + 4 * k4);
            __half2* d = (__half2*)&Xs[nd * XS + 4 * k4];
            d[0] = __floats2half2_rn(v.x, v.y);
            d[1] = __floats2half2_rn(v.z, v.w);
        }
        for (int idx = t; idx < KC * OUT; idx += 256) {
            int k = idx >> 5, nn = idx & 31;
            Wt[nn * XS + k] = __float2half(W[(ch * KC + k) * OUT + nn]);
        }
        __syncthreads();

        uint32_t aaddr = smem_u32(&Xs[(mrow + lrow) * XS + lcolh]);
        uint32_t baddr = smem_u32(&Wt[(n0 + lrow) * XS + lcolh]);
#pragma unroll
        for (int k16 = 0; k16 < KC; k16 += 16) {
            uint32_t a0, a1, a2, a3, b0, b1, b2, b3;
            ldmatrix_x4(a0, a1, a2, a3, aaddr + k16 * 2);
            ldmatrix_x4(b0, b1, b2, b3, baddr + k16 * 2);
            mma_f16(c0, a0, a1, a2, a3, b0, b2);
            mma_f16(c1, a0, a1, a2, a3, b1, b3);
        }
        __syncthreads();
    }

    int r0 = node0 + mrow + g;
    int r1 = r0 + 8;
    if (r0 < n) {
        *(__half2*)(g_s16 + (size_t)r0 * OUT + n0 + 2 * tg) =
            __floats2half2_rn(c0[0], c0[1]);
        *(__half2*)(g_s16 + (size_t)r0 * OUT + n0 + 8 + 2 * tg) =
            __floats2half2_rn(c1[0], c1[1]);
    }
    if (r1 < n) {
        *(__half2*)(g_s16 + (size_t)r1 * OUT + n0 + 2 * tg) =
            __floats2half2_rn(c0[2], c0[3]);
        *(__half2*)(g_s16 + (size_t)r1 * OUT + n0 + 8 + 2 * tg) =
            __floats2half2_rn(c1[2], c1[3]);
    }
}

// ---------------------------------------------------------------------------
// Unified fp16-TC gemm for layers 2/3: g_s16[n,OUT] = relu(g_h)[n,IN] @ W
// Block = 256 thr, 128-node tile; warp w owns rows [w*16, w*16+16), full OUT.
// ---------------------------------------------------------------------------
template <int IN, int OUT>
__global__ void __launch_bounds__(256)
gemm_tc_kernel(const float* __restrict__ W, int n) {
    constexpr int XS = IN + 8;           // 40 / 56: conflict-free ldmatrix strides
    constexpr int NT = OUT / 16;         // n16 tiles (3 / 4)
    __shared__ __align__(16) __half Xs[128 * XS];
    __shared__ __align__(16) __half Wt[OUT * XS];

    const float* __restrict__ X = (const float*)g_h;
    const int t = threadIdx.x;
    const int lane = t & 31;
    const int w = t >> 5;
    const int mrow = w << 4;
    const int g = lane >> 2;
    const int tg = lane & 3;
    const int node0 = blockIdx.x * 128;
    const int lrow = lane & 15;
    const int lcolh = (lane >> 4) << 3;

    // stage X (relu folded)
    for (int idx = t; idx < 128 * IN / 4; idx += 256) {
        int nd = idx / (IN / 4), k4 = idx % (IN / 4);
        int gn = node0 + nd;
        float4 v = make_float4(0.f, 0.f, 0.f, 0.f);
        if (gn < n)
            v = *(const float4*)(X + (size_t)gn * IN + 4 * k4);
        __half2* d = (__half2*)&Xs[nd * XS + 4 * k4];
        d[0] = __floats2half2_rn(fmaxf(v.x, 0.f), fmaxf(v.y, 0.f));
        d[1] = __floats2half2_rn(fmaxf(v.z, 0.f), fmaxf(v.w, 0.f));
    }
    // stage W transposed
    for (int idx = t; idx < IN * OUT; idx += 256) {
        int k = idx / OUT, nn = idx % OUT;
        Wt[nn * XS + k] = __float2half(W[k * OUT + nn]);
    }
    __syncthreads();

    float c[2 * NT][4];
#pragma unroll
    for (int i = 0; i < 2 * NT; i++)
#pragma unroll
        for (int q = 0; q < 4; q++) c[i][q] = 0.f;

    uint32_t aaddr = smem_u32(&Xs[(mrow + lrow) * XS + lcolh]);
#pragma unroll
    for (int k16 = 0; k16 < IN; k16 += 16) {
        uint32_t a0, a1, a2, a3;
        ldmatrix_x4(a0, a1, a2, a3, aaddr + k16 * 2);
#pragma unroll
        for (int nt = 0; nt < NT; nt++) {
            uint32_t b0, b1, b2, b3;
            uint32_t baddr = smem_u32(&Wt[(nt * 16 + lrow) * XS + lcolh]);
            ldmatrix_x4(b0, b1, b2, b3, baddr + k16 * 2);
            mma_f16(c[2 * nt + 0], a0, a1, a2, a3, b0, b2);
            mma_f16(c[2 * nt + 1], a0, a1, a2, a3, b1, b3);
        }
    }

    int r0 = node0 + mrow + g;
    int r1 = r0 + 8;
#pragma unroll
    for (int nt = 0; nt < NT; nt++) {
        if (r0 < n) {
            *(__half2*)(g_s16 + (size_t)r0 * OUT + nt * 16 + 2 * tg) =
                __floats2half2_rn(c[2 * nt][0], c[2 * nt][1]);
            *(__half2*)(g_s16 + (size_t)r0 * OUT + nt * 16 + 8 + 2 * tg) =
                __floats2half2_rn(c[2 * nt + 1][0], c[2 * nt + 1][1]);
        }
        if (r1 < n) {
            *(__half2*)(g_s16 + (size_t)r1 * OUT + nt * 16 + 2 * tg) =
                __floats2half2_rn(c[2 * nt][2], c[2 * nt][3]);
            *(__half2*)(g_s16 + (size_t)r1 * OUT + nt * 16 + 8 + 2 * tg) =
                __floats2half2_rn(c[2 * nt + 1][2], c[2 * nt + 1][3]);
        }
    }
}

// ---------------------------------------------------------------------------
// CSR prep
// ---------------------------------------------------------------------------
__global__ void __launch_bounds__(256)
count_kernel(const int* __restrict__ row, int E) {
    int e0 = (blockIdx.x * 256 + threadIdx.x) * 4;
    if (e0 + 3 < E) {
        int4 r = *(const int4*)(row + e0);
        atomicAdd(&g_cnt[r.x], 1);
        atomicAdd(&g_cnt[r.y], 1);
        atomicAdd(&g_cnt[r.z], 1);
        atomicAdd(&g_cnt[r.w], 1);
    } else {
        for (int e = e0; e < E; e++) atomicAdd(&g_cnt[row[e]], 1);
    }
}

// scan: ptr/fill from cnt, then ZERO cnt (clean for next replay); ysum in blk 0
__global__ void __launch_bounds__(256)
scan_kernel(int n) {
    __shared__ int s[256];
    __shared__ int base;
    int t = threadIdx.x;
    int i = blockIdx.x * 256 + t;
    if (blockIdx.x == 0 && t < 64) g_ysum[t] = 0.f;
    int v = (i < n) ? g_cnt[i] : 0;
    s[t] = v;
    __syncthreads();
#pragma unroll
    for (int off = 1; off < 256; off <<= 1) {
        int tmp = (t >= off) ? s[t - off] : 0;
        __syncthreads();
        s[t] += tmp;
        __syncthreads();
    }
    if (t == 255) base = atomicAdd(&g_total, s[255]);
    __syncthreads();
    if (i < n) {
        int p = base + s[t] - v;
        g_ptr[i] = p;
        g_fill[i] = p;
        g_cnt[i] = 0;
    }
}

// gemm1 (fp16 TC) fused with fill; also re-zeroes g_total for next replay
__global__ void __launch_bounds__(256)
gemm1_fill_kernel(const float* __restrict__ x, const float* __restrict__ W1,
                  const int* __restrict__ row, const int* __restrict__ col,
                  const float* __restrict__ ev, int n, int gG, int E) {
    if (blockIdx.x < gG) {
        gemm1_tc_body(x, W1, n, blockIdx.x);
        return;
    }
    if (blockIdx.x == gG && threadIdx.x == 0) g_total = 0;
    int e0 = ((blockIdx.x - gG) * 256 + threadIdx.x) * 2;
    if (e0 + 1 < E) {
        int2   r = *(const int2*)(row + e0);
        int2   c = *(const int2*)(col + e0);
        float2 v = *(const float2*)(ev + e0);
        int p0 = atomicAdd(&g_fill[r.x], 1);
        g_epack[p0] = ((long long)__float_as_int(v.x) << 32) | (unsigned int)c.x;
        int p1 = atomicAdd(&g_fill[r.y], 1);
        g_epack[p1] = ((long long)__float_as_int(v.y) << 32) | (unsigned int)c.y;
    } else {
        for (int e = e0; e < E; e++) {
            int p = atomicAdd(&g_fill[row[e]], 1);
            g_epack[p] = ((long long)__float_as_int(ev[e]) << 32) |
                         (unsigned int)col[e];
        }
    }
}

// ---------------------------------------------------------------------------
// Gather one feature-lane's share of a support row (LF fp16) and fma.
// ---------------------------------------------------------------------------
template <int LF>
__device__ __forceinline__ void gather_fma(float* acc, const char* rowp, float v) {
    if (LF == 8) {
        uint4 u = __ldg((const uint4*)rowp);
        const __half2* h = (const __half2*)&u;
#pragma unroll
        for (int i = 0; i < 4; i++) {
            float2 s = __half22float2(h[i]);
            acc[2 * i + 0] = fmaf(v, s.x, acc[2 * i + 0]);
            acc[2 * i + 1] = fmaf(v, s.y, acc[2 * i + 1]);
        }
    } else if (LF == 12) {
        uint2 u0 = __ldg((const uint2*)rowp);
        uint2 u1 = __ldg((const uint2*)(rowp + 8));
        uint2 u2 = __ldg((const uint2*)(rowp + 16));
        uint2 us[3] = {u0, u1, u2};
#pragma unroll
        for (int q = 0; q < 3; q++) {
            const __half2* h = (const __half2*)&us[q];
#pragma unroll
            for (int i = 0; i < 2; i++) {
                float2 s = __half22float2(h[i]);
                acc[q * 4 + 2 * i + 0] = fmaf(v, s.x, acc[q * 4 + 2 * i + 0]);
                acc[q * 4 + 2 * i + 1] = fmaf(v, s.y, acc[q * 4 + 2 * i + 1]);
            }
        }
    } else {   // LF == 16
        uint4 u0 = __ldg((const uint4*)rowp);
        uint4 u1 = __ldg((const uint4*)(rowp + 16));
        const __half2* h0 = (const __half2*)&u0;
        const __half2* h1 = (const __half2*)&u1;
#pragma unroll
        for (int i = 0; i < 4; i++) {
            float2 s = __half22float2(h0[i]);
            acc[2 * i + 0] = fmaf(v, s.x, acc[2 * i + 0]);
            acc[2 * i + 1] = fmaf(v, s.y, acc[2 * i + 1]);
        }
#pragma unroll
        for (int i = 0; i < 4; i++) {
            float2 s = __half22float2(h1[i]);
            acc[8 + 2 * i + 0] = fmaf(v, s.x, acc[8 + 2 * i + 0]);
            acc[8 + 2 * i + 1] = fmaf(v, s.y, acc[8 + 2 * i + 1]);
        }
    }
}

// ---------------------------------------------------------------------------
// SpMM (layers 1,2): 8 lanes/node = 2 edge-lanes x 4 feature-lanes.
// 4-deep unroll per edge-lane (8 gather chains per node in flight).
// Row end comes from g_fill (== ptr + cnt after fill).
// ---------------------------------------------------------------------------
template <int F>
__global__ void __launch_bounds__(256)
spmm_kernel(const float* __restrict__ b, int n) {
    constexpr int LF = F / 4;
    int gid = (blockIdx.x * 256 + threadIdx.x) >> 3;
    int l = threadIdx.x & 7;
    int el = l & 1, fl = l >> 1;
    bool active = (gid < n);

    float acc[LF];
#pragma unroll
    for (int i = 0; i < LF; i++)
        acc[i] = (el == 0) ? __ldg(&b[fl * LF + i]) : 0.f;

    const char* __restrict__ S = (const char*)g_s16;
    const int laneoff = fl * LF * 2;

    if (active) {
        int p = g_ptr[gid];
        int end = g_fill[gid];
        int j = p + el;
        for (; j + 6 < end; j += 8) {
            long long ep0 = __ldg(&g_epack[j]);
            long long ep1 = __ldg(&g_epack[j + 2]);
            long long ep2 = __ldg(&g_epack[j + 4]);
            long long ep3 = __ldg(&g_epack[j + 6]);
            gather_fma<LF>(acc, S + (size_t)(int)ep0 * (F * 2) + laneoff,
                           __int_as_float((int)(ep0 >> 32)));
            gather_fma<LF>(acc, S + (size_t)(int)ep1 * (F * 2) + laneoff,
                           __int_as_float((int)(ep1 >> 32)));
            gather_fma<LF>(acc, S + (size_t)(int)ep2 * (F * 2) + laneoff,
                           __int_as_float((int)(ep2 >> 32)));
            gather_fma<LF>(acc, S + (size_t)(int)ep3 * (F * 2) + laneoff,
                           __int_as_float((int)(ep3 >> 32)));
        }
        for (; j < end; j += 2) {
            long long ep = __ldg(&g_epack[j]);
            gather_fma<LF>(acc, S + (size_t)(int)ep * (F * 2) + laneoff,
                           __int_as_float((int)(ep >> 32)));
        }
    }

#pragma unroll
    for (int i = 0; i < LF; i++)
        acc[i] += __shfl_xor_sync(0xffffffffu, acc[i], 1);

    if (active && el == 0) {
        float4* H = (float4*)(g_h + (size_t)gid * F + fl * LF);
#pragma unroll
        for (int i = 0; i < LF / 4; i++)
            H[i] = make_float4(acc[4 * i], acc[4 * i + 1],
                               acc[4 * i + 2], acc[4 * i + 3]);
    }
}

// ---------------------------------------------------------------------------
// Layer-3 SpMM fused with mean pool (F=64): 8 lanes/node, 32 groups/block.
// ---------------------------------------------------------------------------
__global__ void __launch_bounds__(256)
spmm3_pool_kernel(const float* __restrict__ b, int n) {
    constexpr int LF = 16;
    int l = threadIdx.x & 7;
    int el = l & 1, fl = l >> 1;
    int g = threadIdx.x >> 3;            // group in block, 0..31
    const char* __restrict__ S = (const char*)g_s16;
    const int laneoff = fl * LF * 2;

    float bias[LF], ys[LF];
#pragma unroll
    for (int i = 0; i < LF; i++) {
        bias[i] = (el == 0) ? __ldg(&b[fl * LF + i]) : 0.f;
        ys[i] = 0.f;
    }

    for (int node = blockIdx.x * 32 + g; node < n; node += gridDim.x * 32) {
        float acc[LF];
#pragma unroll
        for (int i = 0; i < LF; i++) acc[i] = bias[i];

        int p = g_ptr[node];
        int end = g_fill[node];
        int j = p + el;
        for (; j + 6 < end; j += 8) {
            long long ep0 = __ldg(&g_epack[j]);
            long long ep1 = __ldg(&g_epack[j + 2]);
            long long ep2 = __ldg(&g_epack[j + 4]);
            long long ep3 = __ldg(&g_epack[j + 6]);
            gather_fma<LF>(acc, S + (size_t)(int)ep0 * 128 + laneoff,
                           __int_as_float((int)(ep0 >> 32)));
            gather_fma<LF>(acc, S + (size_t)(int)ep1 * 128 + laneoff,
                           __int_as_float((int)(ep1 >> 32)));
            gather_fma<LF>(acc, S + (size_t)(int)ep2 * 128 + laneoff,
                           __int_as_float((int)(ep2 >> 32)));
            gather_fma<LF>(acc, S + (size_t)(int)ep3 * 128 + laneoff,
                           __int_as_float((int)(ep3 >> 32)));
        }
        for (; j < end; j += 2) {
            long long ep = __ldg(&g_epack[j]);
            gather_fma<LF>(acc, S + (size_t)(int)ep * 128 + laneoff,
                           __int_as_float((int)(ep >> 32)));
        }
#pragma unroll
        for (int i = 0; i < LF; i++) {
            float s = acc[i] + __shfl_xor_sync(0xffffffffu, acc[i], 1);
            ys[i] += fmaxf(s, 0.f);
        }
    }

    __shared__ float sm[128 * LF];
    if (el == 0) {
#pragma unroll
        for (int i = 0; i < LF; i++) sm[(g * 4 + fl) * LF + i] = ys[i];
    }
    __syncthreads();
    if (threadIdx.x < 64) {
        int ll = threadIdx.x >> 4;       // feature lane 0..3
        int slot = threadIdx.x & 15;
        float s = 0.f;
#pragma unroll 16
        for (int gg = 0; gg < 32; gg++) s += sm[(gg * 4 + ll) * LF + slot];
        atomicAdd(&g_ysum[ll * LF + slot], s);
    }
}

// ---------------------------------------------------------------------------
// head
// ---------------------------------------------------------------------------
__global__ void head_kernel(const float* __restrict__ fc1W, const float* __restrict__ fc1b,
                            const float* __restrict__ fc2W, const float* __restrict__ fc2b,
                            float* __restrict__ out, float invN) {
    __shared__ float y[64];
    __shared__ float z1[32];
    __shared__ float z2[2];
    int t = threadIdx.x;
    y[t] = g_ysum[t] * invN;
    __syncthreads();
    if (t < 32) {
        float a = fc1b[t];
#pragma unroll
        for (int i = 0; i < 64; i++) a = fmaf(y[i], fc1W[i * 32 + t], a);
        z1[t] = fmaxf(a, 0.f);
    }
    __syncthreads();
    if (t < 2) {
        float a = fc2b[t];
#pragma unroll
        for (int i = 0; i < 32; i++) a = fmaf(z1[i], fc2W[i * 2 + t], a);
        z2[t] = a;
    }
    __syncthreads();
    if (t == 0) {
        float m = fmaxf(z2[0], z2[1]);
        float e0 = __expf(z2[0] - m), e1 = __expf(z2[1] - m);
        float inv = 1.f / (e0 + e1);
        out[0] = e0 * inv;
        out[1] = e1 * inv;
    }
}

// ---------------------------------------------------------------------------
extern "C" void kernel_launch(void* const* d_in, const int* in_sizes, int n_in,
                              void* d_out, int out_size) {
    const float* x    = (const float*)d_in[0];
    const int*   row  = (const int*)d_in[1];
    const int*   col  = (const int*)d_in[2];
    const float* ev   = (const float*)d_in[3];
    const float* W1   = (const float*)d_in[4];
    const float* b1   = (const float*)d_in[5];
    const float* W2   = (const float*)d_in[6];
    const float* b2   = (const float*)d_in[7];
    const float* W3   = (const float*)d_in[8];
    const float* b3   = (const float*)d_in[9];
    const float* fc1W = (const float*)d_in[10];
    const float* fc1b = (const float*)d_in[11];
    const float* fc2W = (const float*)d_in[12];
    const float* fc2b = (const float*)d_in[13];
    float* out = (float*)d_out;

    int N = in_sizes[0] / 256;   // NFEAT = 256
    int E = in_sizes[1];

    int nbN   = (N + 255) / 256;                 // 391
    int gG    = (N + 63) / 64;                   // 1563 (gemm1 blocks)
    int gG2   = (N + 127) / 128;                 // 782  (gemm2/3 blocks)
    int cntB  = (E + 1023) / 1024;               // 1563
    int fillB = (E / 2 + 255) / 256;             // 3125
    int spB   = (N * 8 + 255) / 256;             // 3125

    count_kernel<<<cntB, 256>>>(row, E);
    scan_kernel<<<nbN, 256>>>(N);
    gemm1_fill_kernel<<<gG + fillB, 256>>>(x, W1, row, col, ev, N, gG, E);

    spmm_kernel<32><<<spB, 256>>>(b1, N);
    gemm_tc_kernel<32, 48><<<gG2, 256>>>(W2, N);
    spmm_kernel<48><<<spB, 256>>>(b2, N);
    gemm_tc_kernel<48, 64><<<gG2, 256>>>(W3, N);
    spmm3_pool_kernel<<<1184, 256>>>(b3, N);
    head_kernel<<<1, 64>>>(fc1W, fc1b, fc2W, fc2b, out, 1.0f / (float)N);
}

// round 12
// speedup vs baseline: 2.1998x; 1.0706x over previous
#include <cuda_runtime.h>
#include <cuda_fp16.h>
#include <cstdint>

// ---------------------------------------------------------------------------
// GCN, round 12:
//  - SpMM accumulates in fp16 (HFMA2): ~2.5x fewer instructions per edge.
//    Edge value pre-splatted to half2 at fill time. Bias added fp32 per node.
//  - Hidden h stored fp16 (g_h16); gemm2/3 stage from fp16 w/ hmax2 relu.
//  - All gemms fp16 TC (m16n8k16 + ldmatrix.x4); layer-3 SpMM fused w/ pool.
// ---------------------------------------------------------------------------

#define MAXN 100000
#define MAXE 1600000

__device__ __align__(16) __half g_s16[(size_t)MAXN * 64];  // gemm out (fp16)
__device__ __align__(16) __half g_h16[(size_t)MAXN * 64];  // spmm out (fp16)
__device__ float g_ysum[64];

__device__ int g_cnt[MAXN];     // zeroed by scan after read (static-0 at load)
__device__ int g_ptr[MAXN];     // row start
__device__ int g_fill[MAXN];    // fill cursor; == row end after fill
__device__ int g_total;         // re-zeroed inside gemm1_fill
__device__ __align__(16) long long g_epack[MAXE];   // (half2splat(val)<<32)|col

// ---- fp16 mma helpers -----------------------------------------------------
__device__ __forceinline__ uint32_t smem_u32(const void* p) {
    return (uint32_t)__cvta_generic_to_shared(p);
}
__device__ __forceinline__ void ldmatrix_x4(uint32_t& r0, uint32_t& r1,
                                            uint32_t& r2, uint32_t& r3,
                                            uint32_t addr) {
    asm volatile("ldmatrix.sync.aligned.m8n8.x4.shared.b16 {%0,%1,%2,%3}, [%4];"
                 : "=r"(r0), "=r"(r1), "=r"(r2), "=r"(r3) : "r"(addr));
}
__device__ __forceinline__ void mma_f16(float* c, uint32_t a0, uint32_t a1,
                                        uint32_t a2, uint32_t a3,
                                        uint32_t b0, uint32_t b1) {
    asm("mma.sync.aligned.m16n8k16.row.col.f32.f16.f16.f32 "
        "{%0,%1,%2,%3}, {%4,%5,%6,%7}, {%8,%9}, {%0,%1,%2,%3};"
        : "+f"(c[0]), "+f"(c[1]), "+f"(c[2]), "+f"(c[3])
        : "r"(a0), "r"(a1), "r"(a2), "r"(a3), "r"(b0), "r"(b1));
}

// ---------------------------------------------------------------------------
// gemm1 (fp16 TC): g_s16[n,32] = X[n,256] @ W[256,32]
// ---------------------------------------------------------------------------
__device__ __forceinline__ void gemm1_tc_body(const float* __restrict__ X,
                                              const float* __restrict__ W,
                                              int n, int bid) {
    constexpr int IN = 256, OUT = 32, KC = 128;
    constexpr int XS = KC + 8;
    __shared__ __align__(16) __half Xs[64 * XS];
    __shared__ __align__(16) __half Wt[32 * XS];

    const int t = threadIdx.x;
    const int lane = t & 31;
    const int w = t >> 5;
    const int mrow = (w & 3) << 4;
    const int n0 = (w >> 2) << 4;
    const int g = lane >> 2;
    const int tg = lane & 3;
    const int node0 = bid * 64;
    const int lrow = lane & 15;
    const int lcolh = (lane >> 4) << 3;

    float c0[4] = {0.f, 0.f, 0.f, 0.f};
    float c1[4] = {0.f, 0.f, 0.f, 0.f};

    for (int ch = 0; ch < IN / KC; ch++) {
        for (int idx = t; idx < 64 * KC / 4; idx += 256) {
            int nd = idx / (KC / 4), k4 = idx % (KC / 4);
            int gn = node0 + nd;
            float4 v = make_float4(0.f, 0.f, 0.f, 0.f);
            if (gn < n)
                v = *(const float4*)(X + (size_t)gn * IN + ch * KC + 4 * k4);
            __half2* d = (__half2*)&Xs[nd * XS + 4 * k4];
            d[0] = __floats2half2_rn(v.x, v.y);
            d[1] = __floats2half2_rn(v.z, v.w);
        }
        for (int idx = t; idx < KC * OUT; idx += 256) {
            int k = idx >> 5, nn = idx & 31;
            Wt[nn * XS + k] = __float2half(W[(ch * KC + k) * OUT + nn]);
        }
        __syncthreads();

        uint32_t aaddr = smem_u32(&Xs[(mrow + lrow) * XS + lcolh]);
        uint32_t baddr = smem_u32(&Wt[(n0 + lrow) * XS + lcolh]);
#pragma unroll
        for (int k16 = 0; k16 < KC; k16 += 16) {
            uint32_t a0, a1, a2, a3, b0, b1, b2, b3;
            ldmatrix_x4(a0, a1, a2, a3, aaddr + k16 * 2);
            ldmatrix_x4(b0, b1, b2, b3, baddr + k16 * 2);
            mma_f16(c0, a0, a1, a2, a3, b0, b2);
            mma_f16(c1, a0, a1, a2, a3, b1, b3);
        }
        __syncthreads();
    }

    int r0 = node0 + mrow + g;
    int r1 = r0 + 8;
    if (r0 < n) {
        *(__half2*)(g_s16 + (size_t)r0 * OUT + n0 + 2 * tg) =
            __floats2half2_rn(c0[0], c0[1]);
        *(__half2*)(g_s16 + (size_t)r0 * OUT + n0 + 8 + 2 * tg) =
            __floats2half2_rn(c1[0], c1[1]);
    }
    if (r1 < n) {
        *(__half2*)(g_s16 + (size_t)r1 * OUT + n0 + 2 * tg) =
            __floats2half2_rn(c0[2], c0[3]);
        *(__half2*)(g_s16 + (size_t)r1 * OUT + n0 + 8 + 2 * tg) =
            __floats2half2_rn(c1[2], c1[3]);
    }
}

// ---------------------------------------------------------------------------
// Unified fp16-TC gemm for layers 2/3: g_s16[n,OUT] = relu(g_h16)[n,IN] @ W
// X staged from fp16 with hmax2 relu.
// ---------------------------------------------------------------------------
template <int IN, int OUT>
__global__ void __launch_bounds__(256)
gemm_tc_kernel(const float* __restrict__ W, int n) {
    constexpr int XS = IN + 8;
    constexpr int NT = OUT / 16;
    __shared__ __align__(16) __half Xs[128 * XS];
    __shared__ __align__(16) __half Wt[OUT * XS];

    const int t = threadIdx.x;
    const int lane = t & 31;
    const int w = t >> 5;
    const int mrow = w << 4;
    const int g = lane >> 2;
    const int tg = lane & 3;
    const int node0 = blockIdx.x * 128;
    const int lrow = lane & 15;
    const int lcolh = (lane >> 4) << 3;

    const __half2 zz = __float2half2_rn(0.f);
    // stage X from fp16 (relu folded), 8 halves per idx
    for (int idx = t; idx < 128 * IN / 8; idx += 256) {
        int nd = idx / (IN / 8), k8 = idx % (IN / 8);
        int gn = node0 + nd;
        uint4 u = make_uint4(0u, 0u, 0u, 0u);
        if (gn < n)
            u = *(const uint4*)((const char*)g_h16 + ((size_t)gn * IN + 8 * k8) * 2);
        __half2* h = (__half2*)&u;
#pragma unroll
        for (int q = 0; q < 4; q++) h[q] = __hmax2(h[q], zz);
        *(uint4*)&Xs[nd * XS + 8 * k8] = u;
    }
    for (int idx = t; idx < IN * OUT; idx += 256) {
        int k = idx / OUT, nn = idx % OUT;
        Wt[nn * XS + k] = __float2half(W[k * OUT + nn]);
    }
    __syncthreads();

    float c[2 * NT][4];
#pragma unroll
    for (int i = 0; i < 2 * NT; i++)
#pragma unroll
        for (int q = 0; q < 4; q++) c[i][q] = 0.f;

    uint32_t aaddr = smem_u32(&Xs[(mrow + lrow) * XS + lcolh]);
#pragma unroll
    for (int k16 = 0; k16 < IN; k16 += 16) {
        uint32_t a0, a1, a2, a3;
        ldmatrix_x4(a0, a1, a2, a3, aaddr + k16 * 2);
#pragma unroll
        for (int nt = 0; nt < NT; nt++) {
            uint32_t b0, b1, b2, b3;
            uint32_t baddr = smem_u32(&Wt[(nt * 16 + lrow) * XS + lcolh]);
            ldmatrix_x4(b0, b1, b2, b3, baddr + k16 * 2);
            mma_f16(c[2 * nt + 0], a0, a1, a2, a3, b0, b2);
            mma_f16(c[2 * nt + 1], a0, a1, a2, a3, b1, b3);
        }
    }

    int r0 = node0 + mrow + g;
    int r1 = r0 + 8;
#pragma unroll
    for (int nt = 0; nt < NT; nt++) {
        if (r0 < n) {
            *(__half2*)(g_s16 + (size_t)r0 * OUT + nt * 16 + 2 * tg) =
                __floats2half2_rn(c[2 * nt][0], c[2 * nt][1]);
            *(__half2*)(g_s16 + (size_t)r0 * OUT + nt * 16 + 8 + 2 * tg) =
                __floats2half2_rn(c[2 * nt + 1][0], c[2 * nt + 1][1]);
        }
        if (r1 < n) {
            *(__half2*)(g_s16 + (size_t)r1 * OUT + nt * 16 + 2 * tg) =
                __floats2half2_rn(c[2 * nt][2], c[2 * nt][3]);
            *(__half2*)(g_s16 + (size_t)r1 * OUT + nt * 16 + 8 + 2 * tg) =
                __floats2half2_rn(c[2 * nt + 1][2], c[2 * nt + 1][3]);
        }
    }
}

// ---------------------------------------------------------------------------
// CSR prep
// ---------------------------------------------------------------------------
__global__ void __launch_bounds__(256)
count_kernel(const int* __restrict__ row, int E) {
    int e0 = (blockIdx.x * 256 + threadIdx.x) * 4;
    if (e0 + 3 < E) {
        int4 r = *(const int4*)(row + e0);
        atomicAdd(&g_cnt[r.x], 1);
        atomicAdd(&g_cnt[r.y], 1);
        atomicAdd(&g_cnt[r.z], 1);
        atomicAdd(&g_cnt[r.w], 1);
    } else {
        for (int e = e0; e < E; e++) atomicAdd(&g_cnt[row[e]], 1);
    }
}

__global__ void __launch_bounds__(256)
scan_kernel(int n) {
    __shared__ int s[256];
    __shared__ int base;
    int t = threadIdx.x;
    int i = blockIdx.x * 256 + t;
    if (blockIdx.x == 0 && t < 64) g_ysum[t] = 0.f;
    int v = (i < n) ? g_cnt[i] : 0;
    s[t] = v;
    __syncthreads();
#pragma unroll
    for (int off = 1; off < 256; off <<= 1) {
        int tmp = (t >= off) ? s[t - off] : 0;
        __syncthreads();
        s[t] += tmp;
        __syncthreads();
    }
    if (t == 255) base = atomicAdd(&g_total, s[255]);
    __syncthreads();
    if (i < n) {
        int p = base + s[t] - v;
        g_ptr[i] = p;
        g_fill[i] = p;
        g_cnt[i] = 0;
    }
}

__device__ __forceinline__ long long pack_edge(float v, int c) {
    __half2 h = __float2half2_rn(v);
    uint32_t u = *reinterpret_cast<uint32_t*>(&h);
    return ((long long)u << 32) | (unsigned int)c;
}

// gemm1 (fp16 TC) fused with fill; re-zeroes g_total
__global__ void __launch_bounds__(256)
gemm1_fill_kernel(const float* __restrict__ x, const float* __restrict__ W1,
                  const int* __restrict__ row, const int* __restrict__ col,
                  const float* __restrict__ ev, int n, int gG, int E) {
    if (blockIdx.x < gG) {
        gemm1_tc_body(x, W1, n, blockIdx.x);
        return;
    }
    if (blockIdx.x == gG && threadIdx.x == 0) g_total = 0;
    int e0 = ((blockIdx.x - gG) * 256 + threadIdx.x) * 2;
    if (e0 + 1 < E) {
        int2   r = *(const int2*)(row + e0);
        int2   c = *(const int2*)(col + e0);
        float2 v = *(const float2*)(ev + e0);
        int p0 = atomicAdd(&g_fill[r.x], 1);
        g_epack[p0] = pack_edge(v.x, c.x);
        int p1 = atomicAdd(&g_fill[r.y], 1);
        g_epack[p1] = pack_edge(v.y, c.y);
    } else {
        for (int e = e0; e < E; e++) {
            int p = atomicAdd(&g_fill[row[e]], 1);
            g_epack[p] = pack_edge(ev[e], col[e]);
        }
    }
}

// ---------------------------------------------------------------------------
// Gather one feature-lane's share (LF fp16) and HFMA2-accumulate.
// ---------------------------------------------------------------------------
template <int LF>
__device__ __forceinline__ void gather_hfma(__half2* acc, const char* rowp,
                                            uint32_t vhu) {
    __half2 vh = *reinterpret_cast<__half2*>(&vhu);
    if (LF == 8) {
        uint4 u = __ldg((const uint4*)rowp);
        const __half2* h = (const __half2*)&u;
#pragma unroll
        for (int i = 0; i < 4; i++) acc[i] = __hfma2(h[i], vh, acc[i]);
    } else if (LF == 12) {
        uint2 u0 = __ldg((const uint2*)rowp);
        uint2 u1 = __ldg((const uint2*)(rowp + 8));
        uint2 u2 = __ldg((const uint2*)(rowp + 16));
        const __half2* h0 = (const __half2*)&u0;
        const __half2* h1 = (const __half2*)&u1;
        const __half2* h2 = (const __half2*)&u2;
        acc[0] = __hfma2(h0[0], vh, acc[0]);
        acc[1] = __hfma2(h0[1], vh, acc[1]);
        acc[2] = __hfma2(h1[0], vh, acc[2]);
        acc[3] = __hfma2(h1[1], vh, acc[3]);
        acc[4] = __hfma2(h2[0], vh, acc[4]);
        acc[5] = __hfma2(h2[1], vh, acc[5]);
    } else {   // LF == 16
        uint4 u0 = __ldg((const uint4*)rowp);
        uint4 u1 = __ldg((const uint4*)(rowp + 16));
        const __half2* h0 = (const __half2*)&u0;
        const __half2* h1 = (const __half2*)&u1;
#pragma unroll
        for (int i = 0; i < 4; i++) acc[i] = __hfma2(h0[i], vh, acc[i]);
#pragma unroll
        for (int i = 0; i < 4; i++) acc[4 + i] = __hfma2(h1[i], vh, acc[4 + i]);
    }
}

// ---------------------------------------------------------------------------
// SpMM (layers 1,2): 8 lanes/node = 2 edge-lanes x 4 feature-lanes.
// fp16 accumulate; bias added fp32 per node; output fp16 to g_h16.
// ---------------------------------------------------------------------------
template <int F>
__global__ void __launch_bounds__(256)
spmm_kernel(const float* __restrict__ b, int n) {
    constexpr int LF = F / 4;
    constexpr int LH = LF / 2;
    int gid = (blockIdx.x * 256 + threadIdx.x) >> 3;
    int l = threadIdx.x & 7;
    int el = l & 1, fl = l >> 1;
    bool active = (gid < n);

    __half2 acc[LH];
    const __half2 zz = __float2half2_rn(0.f);
#pragma unroll
    for (int i = 0; i < LH; i++) acc[i] = zz;

    const char* __restrict__ S = (const char*)g_s16;
    const int laneoff = fl * LF * 2;

    if (active) {
        int p = g_ptr[gid];
        int end = g_fill[gid];
        int j = p + el;
        for (; j + 6 < end; j += 8) {
            long long ep0 = __ldg(&g_epack[j]);
            long long ep1 = __ldg(&g_epack[j + 2]);
            long long ep2 = __ldg(&g_epack[j + 4]);
            long long ep3 = __ldg(&g_epack[j + 6]);
            gather_hfma<LF>(acc, S + (size_t)(int)ep0 * (F * 2) + laneoff,
                            (uint32_t)(ep0 >> 32));
            gather_hfma<LF>(acc, S + (size_t)(int)ep1 * (F * 2) + laneoff,
                            (uint32_t)(ep1 >> 32));
            gather_hfma<LF>(acc, S + (size_t)(int)ep2 * (F * 2) + laneoff,
                            (uint32_t)(ep2 >> 32));
            gather_hfma<LF>(acc, S + (size_t)(int)ep3 * (F * 2) + laneoff,
                            (uint32_t)(ep3 >> 32));
        }
        for (; j < end; j += 2) {
            long long ep = __ldg(&g_epack[j]);
            gather_hfma<LF>(acc, S + (size_t)(int)ep * (F * 2) + laneoff,
                            (uint32_t)(ep >> 32));
        }
    }

    // combine edge lanes (fp16)
#pragma unroll
    for (int i = 0; i < LH; i++) {
        uint32_t au = *reinterpret_cast<uint32_t*>(&acc[i]);
        uint32_t ou = __shfl_xor_sync(0xffffffffu, au, 1);
        acc[i] = __hadd2(acc[i], *reinterpret_cast<__half2*>(&ou));
    }

    if (active && el == 0) {
        // bias in fp32, restore to fp16
        uint32_t o[LH];
#pragma unroll
        for (int i = 0; i < LH; i++) {
            float2 f = __half22float2(acc[i]);
            float2 bi = *(const float2*)(b + fl * LF + 2 * i);
            __half2 h = __floats2half2_rn(f.x + bi.x, f.y + bi.y);
            o[i] = *reinterpret_cast<uint32_t*>(&h);
        }
        char* H = (char*)g_h16 + ((size_t)gid * F + fl * LF) * 2;
        if (LF == 8) {
            *(uint4*)H = make_uint4(o[0], o[1], o[2], o[3]);
        } else {   // LF == 12
            *(uint2*)H = make_uint2(o[0], o[1]);
            *(uint2*)(H + 8) = make_uint2(o[2], o[3]);
            *(uint2*)(H + 16) = make_uint2(o[4], o[5]);
        }
    }
}

// ---------------------------------------------------------------------------
// Layer-3 SpMM fused with mean pool (F=64): 8 lanes/node, 32 groups/block.
// ---------------------------------------------------------------------------
__global__ void __launch_bounds__(256)
spmm3_pool_kernel(const float* __restrict__ b, int n) {
    constexpr int LF = 16;
    constexpr int LH = 8;
    int l = threadIdx.x & 7;
    int el = l & 1, fl = l >> 1;
    int g = threadIdx.x >> 3;
    const char* __restrict__ S = (const char*)g_s16;
    const int laneoff = fl * LF * 2;
    const __half2 zz = __float2half2_rn(0.f);

    float bias[LF], ys[LF];
#pragma unroll
    for (int i = 0; i < LF; i++) {
        bias[i] = __ldg(&b[fl * LF + i]);
        ys[i] = 0.f;
    }

    for (int node = blockIdx.x * 32 + g; node < n; node += gridDim.x * 32) {
        __half2 acc[LH];
#pragma unroll
        for (int i = 0; i < LH; i++) acc[i] = zz;

        int p = g_ptr[node];
        int end = g_fill[node];
        int j = p + el;
        for (; j + 6 < end; j += 8) {
            long long ep0 = __ldg(&g_epack[j]);
            long long ep1 = __ldg(&g_epack[j + 2]);
            long long ep2 = __ldg(&g_epack[j + 4]);
            long long ep3 = __ldg(&g_epack[j + 6]);
            gather_hfma<LF>(acc, S + (size_t)(int)ep0 * 128 + laneoff,
                            (uint32_t)(ep0 >> 32));
            gather_hfma<LF>(acc, S + (size_t)(int)ep1 * 128 + laneoff,
                            (uint32_t)(ep1 >> 32));
            gather_hfma<LF>(acc, S + (size_t)(int)ep2 * 128 + laneoff,
                            (uint32_t)(ep2 >> 32));
            gather_hfma<LF>(acc, S + (size_t)(int)ep3 * 128 + laneoff,
                            (uint32_t)(ep3 >> 32));
        }
        for (; j < end; j += 2) {
            long long ep = __ldg(&g_epack[j]);
            gather_hfma<LF>(acc, S + (size_t)(int)ep * 128 + laneoff,
                            (uint32_t)(ep >> 32));
        }
#pragma unroll
        for (int i = 0; i < LH; i++) {
            uint32_t au = *reinterpret_cast<uint32_t*>(&acc[i]);
            uint32_t ou = __shfl_xor_sync(0xffffffffu, au, 1);
            __half2 s2 = __hadd2(acc[i], *reinterpret_cast<__half2*>(&ou));
            float2 f = __half22float2(s2);
            ys[2 * i + 0] += fmaxf(f.x + bias[2 * i + 0], 0.f);
            ys[2 * i + 1] += fmaxf(f.y + bias[2 * i + 1], 0.f);
        }
    }

    __shared__ float sm[128 * LF];
    if (el == 0) {
#pragma unroll
        for (int i = 0; i < LF; i++) sm[(g * 4 + fl) * LF + i] = ys[i];
    }
    __syncthreads();
    if (threadIdx.x < 64) {
        int ll = threadIdx.x >> 4;
        int slot = threadIdx.x & 15;
        float s = 0.f;
#pragma unroll 16
        for (int gg = 0; gg < 32; gg++) s += sm[(gg * 4 + ll) * LF + slot];
        atomicAdd(&g_ysum[ll * LF + slot], s);
    }
}

// ---------------------------------------------------------------------------
// head
// ---------------------------------------------------------------------------
__global__ void head_kernel(const float* __restrict__ fc1W, const float* __restrict__ fc1b,
                            const float* __restrict__ fc2W, const float* __restrict__ fc2b,
                            float* __restrict__ out, float invN) {
    __shared__ float y[64];
    __shared__ float z1[32];
    __shared__ float z2[2];
    int t = threadIdx.x;
    y[t] = g_ysum[t] * invN;
    __syncthreads();
    if (t < 32) {
        float a = fc1b[t];
#pragma unroll
        for (int i = 0; i < 64; i++) a = fmaf(y[i], fc1W[i * 32 + t], a);
        z1[t] = fmaxf(a, 0.f);
    }
    __syncthreads();
    if (t < 2) {
        float a = fc2b[t];
#pragma unroll
        for (int i = 0; i < 32; i++) a = fmaf(z1[i], fc2W[i * 2 + t], a);
        z2[t] = a;
    }
    __syncthreads();
    if (t == 0) {
        float m = fmaxf(z2[0], z2[1]);
        float e0 = __expf(z2[0] - m), e1 = __expf(z2[1] - m);
        float inv = 1.f / (e0 + e1);
        out[0] = e0 * inv;
        out[1] = e1 * inv;
    }
}

// ---------------------------------------------------------------------------
extern "C" void kernel_launch(void* const* d_in, const int* in_sizes, int n_in,
                              void* d_out, int out_size) {
    const float* x    = (const float*)d_in[0];
    const int*   row  = (const int*)d_in[1];
    const int*   col  = (const int*)d_in[2];
    const float* ev   = (const float*)d_in[3];
    const float* W1   = (const float*)d_in[4];
    const float* b1   = (const float*)d_in[5];
    const float* W2   = (const float*)d_in[6];
    const float* b2   = (const float*)d_in[7];
    const float* W3   = (const float*)d_in[8];
    const float* b3   = (const float*)d_in[9];
    const float* fc1W = (const float*)d_in[10];
    const float* fc1b = (const float*)d_in[11];
    const float* fc2W = (const float*)d_in[12];
    const float* fc2b = (const float*)d_in[13];
    float* out = (float*)d_out;

    int N = in_sizes[0] / 256;   // NFEAT = 256
    int E = in_sizes[1];

    int nbN   = (N + 255) / 256;                 // 391
    int gG    = (N + 63) / 64;                   // 1563
    int gG2   = (N + 127) / 128;                 // 782
    int cntB  = (E + 1023) / 1024;               // 1563
    int fillB = (E / 2 + 255) / 256;             // 3125
    int spB   = (N * 8 + 255) / 256;             // 3125

    count_kernel<<<cntB, 256>>>(row, E);
    scan_kernel<<<nbN, 256>>>(N);
    gemm1_fill_kernel<<<gG + fillB, 256>>>(x, W1, row, col, ev, N, gG, E);

    spmm_kernel<32><<<spB, 256>>>(b1, N);
    gemm_tc_kernel<32, 48><<<gG2, 256>>>(W2, N);
    spmm_kernel<48><<<spB, 256>>>(b2, N);
    gemm_tc_kernel<48, 64><<<gG2, 256>>>(W3, N);
    spmm3_pool_kernel<<<1184, 256>>>(b3, N);
    head_kernel<<<1, 64>>>(fc1W, fc1b, fc2W, fc2b, out, 1.0f / (float)N);
}

// round 13
// speedup vs baseline: 2.2326x; 1.0149x over previous
#include <cuda_runtime.h>
#include <cuda_fp16.h>
#include <cstdint>

// ---------------------------------------------------------------------------
// GCN, round 13:
//  - SpMM (layers 1,2): 8-deep gather unroll (16 chains/node-group in flight)
//  - gemm1: 128-node tile (halved staging overhead, doubled staging MLP)
//  - fp16 HFMA2 spmm accumulation, fp16 h; all gemms fp16 TC + ldmatrix
// ---------------------------------------------------------------------------

#define MAXN 100000
#define MAXE 1600000

__device__ __align__(16) __half g_s16[(size_t)MAXN * 64];  // gemm out (fp16)
__device__ __align__(16) __half g_h16[(size_t)MAXN * 64];  // spmm out (fp16)
__device__ float g_ysum[64];

__device__ int g_cnt[MAXN];     // zeroed by scan after read (static-0 at load)
__device__ int g_ptr[MAXN];     // row start
__device__ int g_fill[MAXN];    // fill cursor; == row end after fill
__device__ int g_total;         // re-zeroed inside gemm1_fill
__device__ __align__(16) long long g_epack[MAXE];   // (half2splat(val)<<32)|col

// ---- fp16 mma helpers -----------------------------------------------------
__device__ __forceinline__ uint32_t smem_u32(const void* p) {
    return (uint32_t)__cvta_generic_to_shared(p);
}
__device__ __forceinline__ void ldmatrix_x4(uint32_t& r0, uint32_t& r1,
                                            uint32_t& r2, uint32_t& r3,
                                            uint32_t addr) {
    asm volatile("ldmatrix.sync.aligned.m8n8.x4.shared.b16 {%0,%1,%2,%3}, [%4];"
                 : "=r"(r0), "=r"(r1), "=r"(r2), "=r"(r3) : "r"(addr));
}
__device__ __forceinline__ void mma_f16(float* c, uint32_t a0, uint32_t a1,
                                        uint32_t a2, uint32_t a3,
                                        uint32_t b0, uint32_t b1) {
    asm("mma.sync.aligned.m16n8k16.row.col.f32.f16.f16.f32 "
        "{%0,%1,%2,%3}, {%4,%5,%6,%7}, {%8,%9}, {%0,%1,%2,%3};"
        : "+f"(c[0]), "+f"(c[1]), "+f"(c[2]), "+f"(c[3])
        : "r"(a0), "r"(a1), "r"(a2), "r"(a3), "r"(b0), "r"(b1));
}

// ---------------------------------------------------------------------------
// gemm1 (fp16 TC): g_s16[n,32] = X[n,256] @ W[256,32]
// Block = 256 thr, 128-node tile; warp w owns rows [w*16,w*16+16), full OUT.
// K chunked at KC=64.
// ---------------------------------------------------------------------------
__device__ __forceinline__ void gemm1_tc_body(const float* __restrict__ X,
                                              const float* __restrict__ W,
                                              int n, int bid) {
    constexpr int IN = 256, OUT = 32, KC = 64;
    constexpr int XS = KC + 8;   // 72 halves = 144B stride
    __shared__ __align__(16) __half Xs[128 * XS];
    __shared__ __align__(16) __half Wt[32 * XS];

    const int t = threadIdx.x;
    const int lane = t & 31;
    const int w = t >> 5;
    const int mrow = w << 4;
    const int g = lane >> 2;
    const int tg = lane & 3;
    const int node0 = bid * 128;
    const int lrow = lane & 15;
    const int lcolh = (lane >> 4) << 3;

    float c0[4] = {0.f, 0.f, 0.f, 0.f};
    float c1[4] = {0.f, 0.f, 0.f, 0.f};
    float c2[4] = {0.f, 0.f, 0.f, 0.f};
    float c3[4] = {0.f, 0.f, 0.f, 0.f};

    for (int ch = 0; ch < IN / KC; ch++) {
        for (int idx = t; idx < 128 * KC / 4; idx += 256) {
            int nd = idx / (KC / 4), k4 = idx % (KC / 4);
            int gn = node0 + nd;
            float4 v = make_float4(0.f, 0.f, 0.f, 0.f);
            if (gn < n)
                v = *(const float4*)(X + (size_t)gn * IN + ch * KC + 4 * k4);
            __half2* d = (__half2*)&Xs[nd * XS + 4 * k4];
            d[0] = __floats2half2_rn(v.x, v.y);
            d[1] = __floats2half2_rn(v.z, v.w);
        }
        for (int idx = t; idx < KC * OUT; idx += 256) {
            int k = idx >> 5, nn = idx & 31;
            Wt[nn * XS + k] = __float2half(W[(ch * KC + k) * OUT + nn]);
        }
        __syncthreads();

        uint32_t aaddr = smem_u32(&Xs[(mrow + lrow) * XS + lcolh]);
        uint32_t baddr0 = smem_u32(&Wt[lrow * XS + lcolh]);
        uint32_t baddr1 = smem_u32(&Wt[(16 + lrow) * XS + lcolh]);
#pragma unroll
        for (int k16 = 0; k16 < KC; k16 += 16) {
            uint32_t a0, a1, a2, a3, b0, b1, b2, b3;
            ldmatrix_x4(a0, a1, a2, a3, aaddr + k16 * 2);
            ldmatrix_x4(b0, b1, b2, b3, baddr0 + k16 * 2);
            mma_f16(c0, a0, a1, a2, a3, b0, b2);
            mma_f16(c1, a0, a1, a2, a3, b1, b3);
            ldmatrix_x4(b0, b1, b2, b3, baddr1 + k16 * 2);
            mma_f16(c2, a0, a1, a2, a3, b0, b2);
            mma_f16(c3, a0, a1, a2, a3, b1, b3);
        }
        __syncthreads();
    }

    int r0 = node0 + mrow + g;
    int r1 = r0 + 8;
    if (r0 < n) {
        *(__half2*)(g_s16 + (size_t)r0 * OUT + 2 * tg) =
            __floats2half2_rn(c0[0], c0[1]);
        *(__half2*)(g_s16 + (size_t)r0 * OUT + 8 + 2 * tg) =
            __floats2half2_rn(c1[0], c1[1]);
        *(__half2*)(g_s16 + (size_t)r0 * OUT + 16 + 2 * tg) =
            __floats2half2_rn(c2[0], c2[1]);
        *(__half2*)(g_s16 + (size_t)r0 * OUT + 24 + 2 * tg) =
            __floats2half2_rn(c3[0], c3[1]);
    }
    if (r1 < n) {
        *(__half2*)(g_s16 + (size_t)r1 * OUT + 2 * tg) =
            __floats2half2_rn(c0[2], c0[3]);
        *(__half2*)(g_s16 + (size_t)r1 * OUT + 8 + 2 * tg) =
            __floats2half2_rn(c1[2], c1[3]);
        *(__half2*)(g_s16 + (size_t)r1 * OUT + 16 + 2 * tg) =
            __floats2half2_rn(c2[2], c2[3]);
        *(__half2*)(g_s16 + (size_t)r1 * OUT + 24 + 2 * tg) =
            __floats2half2_rn(c3[2], c3[3]);
    }
}

// ---------------------------------------------------------------------------
// Unified fp16-TC gemm for layers 2/3: g_s16[n,OUT] = relu(g_h16)[n,IN] @ W
// ---------------------------------------------------------------------------
template <int IN, int OUT>
__global__ void __launch_bounds__(256)
gemm_tc_kernel(const float* __restrict__ W, int n) {
    constexpr int XS = IN + 8;
    constexpr int NT = OUT / 16;
    __shared__ __align__(16) __half Xs[128 * XS];
    __shared__ __align__(16) __half Wt[OUT * XS];

    const int t = threadIdx.x;
    const int lane = t & 31;
    const int w = t >> 5;
    const int mrow = w << 4;
    const int g = lane >> 2;
    const int tg = lane & 3;
    const int node0 = blockIdx.x * 128;
    const int lrow = lane & 15;
    const int lcolh = (lane >> 4) << 3;

    const __half2 zz = __float2half2_rn(0.f);
    for (int idx = t; idx < 128 * IN / 8; idx += 256) {
        int nd = idx / (IN / 8), k8 = idx % (IN / 8);
        int gn = node0 + nd;
        uint4 u = make_uint4(0u, 0u, 0u, 0u);
        if (gn < n)
            u = *(const uint4*)((const char*)g_h16 + ((size_t)gn * IN + 8 * k8) * 2);
        __half2* h = (__half2*)&u;
#pragma unroll
        for (int q = 0; q < 4; q++) h[q] = __hmax2(h[q], zz);
        *(uint4*)&Xs[nd * XS + 8 * k8] = u;
    }
    for (int idx = t; idx < IN * OUT; idx += 256) {
        int k = idx / OUT, nn = idx % OUT;
        Wt[nn * XS + k] = __float2half(W[k * OUT + nn]);
    }
    __syncthreads();

    float c[2 * NT][4];
#pragma unroll
    for (int i = 0; i < 2 * NT; i++)
#pragma unroll
        for (int q = 0; q < 4; q++) c[i][q] = 0.f;

    uint32_t aaddr = smem_u32(&Xs[(mrow + lrow) * XS + lcolh]);
#pragma unroll
    for (int k16 = 0; k16 < IN; k16 += 16) {
        uint32_t a0, a1, a2, a3;
        ldmatrix_x4(a0, a1, a2, a3, aaddr + k16 * 2);
#pragma unroll
        for (int nt = 0; nt < NT; nt++) {
            uint32_t b0, b1, b2, b3;
            uint32_t baddr = smem_u32(&Wt[(nt * 16 + lrow) * XS + lcolh]);
            ldmatrix_x4(b0, b1, b2, b3, baddr + k16 * 2);
            mma_f16(c[2 * nt + 0], a0, a1, a2, a3, b0, b2);
            mma_f16(c[2 * nt + 1], a0, a1, a2, a3, b1, b3);
        }
    }

    int r0 = node0 + mrow + g;
    int r1 = r0 + 8;
#pragma unroll
    for (int nt = 0; nt < NT; nt++) {
        if (r0 < n) {
            *(__half2*)(g_s16 + (size_t)r0 * OUT + nt * 16 + 2 * tg) =
                __floats2half2_rn(c[2 * nt][0], c[2 * nt][1]);
            *(__half2*)(g_s16 + (size_t)r0 * OUT + nt * 16 + 8 + 2 * tg) =
                __floats2half2_rn(c[2 * nt + 1][0], c[2 * nt + 1][1]);
        }
        if (r1 < n) {
            *(__half2*)(g_s16 + (size_t)r1 * OUT + nt * 16 + 2 * tg) =
                __floats2half2_rn(c[2 * nt][2], c[2 * nt][3]);
            *(__half2*)(g_s16 + (size_t)r1 * OUT + nt * 16 + 8 + 2 * tg) =
                __floats2half2_rn(c[2 * nt + 1][2], c[2 * nt + 1][3]);
        }
    }
}

// ---------------------------------------------------------------------------
// CSR prep
// ---------------------------------------------------------------------------
__global__ void __launch_bounds__(256)
count_kernel(const int* __restrict__ row, int E) {
    int e0 = (blockIdx.x * 256 + threadIdx.x) * 4;
    if (e0 + 3 < E) {
        int4 r = *(const int4*)(row + e0);
        atomicAdd(&g_cnt[r.x], 1);
        atomicAdd(&g_cnt[r.y], 1);
        atomicAdd(&g_cnt[r.z], 1);
        atomicAdd(&g_cnt[r.w], 1);
    } else {
        for (int e = e0; e < E; e++) atomicAdd(&g_cnt[row[e]], 1);
    }
}

__global__ void __launch_bounds__(256)
scan_kernel(int n) {
    __shared__ int s[256];
    __shared__ int base;
    int t = threadIdx.x;
    int i = blockIdx.x * 256 + t;
    if (blockIdx.x == 0 && t < 64) g_ysum[t] = 0.f;
    int v = (i < n) ? g_cnt[i] : 0;
    s[t] = v;
    __syncthreads();
#pragma unroll
    for (int off = 1; off < 256; off <<= 1) {
        int tmp = (t >= off) ? s[t - off] : 0;
        __syncthreads();
        s[t] += tmp;
        __syncthreads();
    }
    if (t == 255) base = atomicAdd(&g_total, s[255]);
    __syncthreads();
    if (i < n) {
        int p = base + s[t] - v;
        g_ptr[i] = p;
        g_fill[i] = p;
        g_cnt[i] = 0;
    }
}

__device__ __forceinline__ long long pack_edge(float v, int c) {
    __half2 h = __float2half2_rn(v);
    uint32_t u = *reinterpret_cast<uint32_t*>(&h);
    return ((long long)u << 32) | (unsigned int)c;
}

// gemm1 (fp16 TC, 128-tile) fused with fill; re-zeroes g_total
__global__ void __launch_bounds__(256)
gemm1_fill_kernel(const float* __restrict__ x, const float* __restrict__ W1,
                  const int* __restrict__ row, const int* __restrict__ col,
                  const float* __restrict__ ev, int n, int gG, int E) {
    if (blockIdx.x < gG) {
        gemm1_tc_body(x, W1, n, blockIdx.x);
        return;
    }
    if (blockIdx.x == gG && threadIdx.x == 0) g_total = 0;
    int e0 = ((blockIdx.x - gG) * 256 + threadIdx.x) * 2;
    if (e0 + 1 < E) {
        int2   r = *(const int2*)(row + e0);
        int2   c = *(const int2*)(col + e0);
        float2 v = *(const float2*)(ev + e0);
        int p0 = atomicAdd(&g_fill[r.x], 1);
        g_epack[p0] = pack_edge(v.x, c.x);
        int p1 = atomicAdd(&g_fill[r.y], 1);
        g_epack[p1] = pack_edge(v.y, c.y);
    } else {
        for (int e = e0; e < E; e++) {
            int p = atomicAdd(&g_fill[row[e]], 1);
            g_epack[p] = pack_edge(ev[e], col[e]);
        }
    }
}

// ---------------------------------------------------------------------------
// Gather one feature-lane's share (LF fp16) and HFMA2-accumulate.
// ---------------------------------------------------------------------------
template <int LF>
__device__ __forceinline__ void gather_hfma(__half2* acc, const char* rowp,
                                            uint32_t vhu) {
    __half2 vh = *reinterpret_cast<__half2*>(&vhu);
    if (LF == 8) {
        uint4 u = __ldg((const uint4*)rowp);
        const __half2* h = (const __half2*)&u;
#pragma unroll
        for (int i = 0; i < 4; i++) acc[i] = __hfma2(h[i], vh, acc[i]);
    } else if (LF == 12) {
        uint2 u0 = __ldg((const uint2*)rowp);
        uint2 u1 = __ldg((const uint2*)(rowp + 8));
        uint2 u2 = __ldg((const uint2*)(rowp + 16));
        const __half2* h0 = (const __half2*)&u0;
        const __half2* h1 = (const __half2*)&u1;
        const __half2* h2 = (const __half2*)&u2;
        acc[0] = __hfma2(h0[0], vh, acc[0]);
        acc[1] = __hfma2(h0[1], vh, acc[1]);
        acc[2] = __hfma2(h1[0], vh, acc[2]);
        acc[3] = __hfma2(h1[1], vh, acc[3]);
        acc[4] = __hfma2(h2[0], vh, acc[4]);
        acc[5] = __hfma2(h2[1], vh, acc[5]);
    } else {   // LF == 16
        uint4 u0 = __ldg((const uint4*)rowp);
        uint4 u1 = __ldg((const uint4*)(rowp + 16));
        const __half2* h0 = (const __half2*)&u0;
        const __half2* h1 = (const __half2*)&u1;
#pragma unroll
        for (int i = 0; i < 4; i++) acc[i] = __hfma2(h0[i], vh, acc[i]);
#pragma unroll
        for (int i = 0; i < 4; i++) acc[4 + i] = __hfma2(h1[i], vh, acc[4 + i]);
    }
}

// ---------------------------------------------------------------------------
// SpMM (layers 1,2): 8 lanes/node = 2 edge-lanes x 4 feature-lanes.
// 8-deep unroll per edge-lane (16 gather chains per node group in flight).
// ---------------------------------------------------------------------------
template <int F>
__global__ void __launch_bounds__(256)
spmm_kernel(const float* __restrict__ b, int n) {
    constexpr int LF = F / 4;
    constexpr int LH = LF / 2;
    int gid = (blockIdx.x * 256 + threadIdx.x) >> 3;
    int l = threadIdx.x & 7;
    int el = l & 1, fl = l >> 1;
    bool active = (gid < n);

    __half2 acc[LH];
    const __half2 zz = __float2half2_rn(0.f);
#pragma unroll
    for (int i = 0; i < LH; i++) acc[i] = zz;

    const char* __restrict__ S = (const char*)g_s16;
    const int laneoff = fl * LF * 2;

    if (active) {
        int p = g_ptr[gid];
        int end = g_fill[gid];
        int j = p + el;
        for (; j + 14 < end; j += 16) {
            long long ep[8];
#pragma unroll
            for (int q = 0; q < 8; q++) ep[q] = __ldg(&g_epack[j + 2 * q]);
#pragma unroll
            for (int q = 0; q < 8; q++)
                gather_hfma<LF>(acc, S + (size_t)(int)ep[q] * (F * 2) + laneoff,
                                (uint32_t)(ep[q] >> 32));
        }
        for (; j < end; j += 2) {
            long long ep = __ldg(&g_epack[j]);
            gather_hfma<LF>(acc, S + (size_t)(int)ep * (F * 2) + laneoff,
                            (uint32_t)(ep >> 32));
        }
    }

#pragma unroll
    for (int i = 0; i < LH; i++) {
        uint32_t au = *reinterpret_cast<uint32_t*>(&acc[i]);
        uint32_t ou = __shfl_xor_sync(0xffffffffu, au, 1);
        acc[i] = __hadd2(acc[i], *reinterpret_cast<__half2*>(&ou));
    }

    if (active && el == 0) {
        uint32_t o[LH];
#pragma unroll
        for (int i = 0; i < LH; i++) {
            float2 f = __half22float2(acc[i]);
            float2 bi = *(const float2*)(b + fl * LF + 2 * i);
            __half2 h = __floats2half2_rn(f.x + bi.x, f.y + bi.y);
            o[i] = *reinterpret_cast<uint32_t*>(&h);
        }
        char* H = (char*)g_h16 + ((size_t)gid * F + fl * LF) * 2;
        if (LF == 8) {
            *(uint4*)H = make_uint4(o[0], o[1], o[2], o[3]);
        } else {   // LF == 12
            *(uint2*)H = make_uint2(o[0], o[1]);
            *(uint2*)(H + 8) = make_uint2(o[2], o[3]);
            *(uint2*)(H + 16) = make_uint2(o[4], o[5]);
        }
    }
}

// ---------------------------------------------------------------------------
// Layer-3 SpMM fused with mean pool (F=64): 8 lanes/node, 32 groups/block.
// ---------------------------------------------------------------------------
__global__ void __launch_bounds__(256)
spmm3_pool_kernel(const float* __restrict__ b, int n) {
    constexpr int LF = 16;
    constexpr int LH = 8;
    int l = threadIdx.x & 7;
    int el = l & 1, fl = l >> 1;
    int g = threadIdx.x >> 3;
    const char* __restrict__ S = (const char*)g_s16;
    const int laneoff = fl * LF * 2;
    const __half2 zz = __float2half2_rn(0.f);

    float bias[LF], ys[LF];
#pragma unroll
    for (int i = 0; i < LF; i++) {
        bias[i] = __ldg(&b[fl * LF + i]);
        ys[i] = 0.f;
    }

    for (int node = blockIdx.x * 32 + g; node < n; node += gridDim.x * 32) {
        __half2 acc[LH];
#pragma unroll
        for (int i = 0; i < LH; i++) acc[i] = zz;

        int p = g_ptr[node];
        int end = g_fill[node];
        int j = p + el;
        for (; j + 6 < end; j += 8) {
            long long ep0 = __ldg(&g_epack[j]);
            long long ep1 = __ldg(&g_epack[j + 2]);
            long long ep2 = __ldg(&g_epack[j + 4]);
            long long ep3 = __ldg(&g_epack[j + 6]);
            gather_hfma<LF>(acc, S + (size_t)(int)ep0 * 128 + laneoff,
                            (uint32_t)(ep0 >> 32));
            gather_hfma<LF>(acc, S + (size_t)(int)ep1 * 128 + laneoff,
                            (uint32_t)(ep1 >> 32));
            gather_hfma<LF>(acc, S + (size_t)(int)ep2 * 128 + laneoff,
                            (uint32_t)(ep2 >> 32));
            gather_hfma<LF>(acc, S + (size_t)(int)ep3 * 128 + laneoff,
                            (uint32_t)(ep3 >> 32));
        }
        for (; j < end; j += 2) {
            long long ep = __ldg(&g_epack[j]);
            gather_hfma<LF>(acc, S + (size_t)(int)ep * 128 + laneoff,
                            (uint32_t)(ep >> 32));
        }
#pragma unroll
        for (int i = 0; i < LH; i++) {
            uint32_t au = *reinterpret_cast<uint32_t*>(&acc[i]);
            uint32_t ou = __shfl_xor_sync(0xffffffffu, au, 1);
            __half2 s2 = __hadd2(acc[i], *reinterpret_cast<__half2*>(&ou));
            float2 f = __half22float2(s2);
            ys[2 * i + 0] += fmaxf(f.x + bias[2 * i + 0], 0.f);
            ys[2 * i + 1] += fmaxf(f.y + bias[2 * i + 1], 0.f);
        }
    }

    __shared__ float sm[128 * LF];
    if (el == 0) {
#pragma unroll
        for (int i = 0; i < LF; i++) sm[(g * 4 + fl) * LF + i] = ys[i];
    }
    __syncthreads();
    if (threadIdx.x < 64) {
        int ll = threadIdx.x >> 4;
        int slot = threadIdx.x & 15;
        float s = 0.f;
#pragma unroll 16
        for (int gg = 0; gg < 32; gg++) s += sm[(gg * 4 + ll) * LF + slot];
        atomicAdd(&g_ysum[ll * LF + slot], s);
    }
}

// ---------------------------------------------------------------------------
// head
// ---------------------------------------------------------------------------
__global__ void head_kernel(const float* __restrict__ fc1W, const float* __restrict__ fc1b,
                            const float* __restrict__ fc2W, const float* __restrict__ fc2b,
                            float* __restrict__ out, float invN) {
    __shared__ float y[64];
    __shared__ float z1[32];
    __shared__ float z2[2];
    int t = threadIdx.x;
    y[t] = g_ysum[t] * invN;
    __syncthreads();
    if (t < 32) {
        float a = fc1b[t];
#pragma unroll
        for (int i = 0; i < 64; i++) a = fmaf(y[i], fc1W[i * 32 + t], a);
        z1[t] = fmaxf(a, 0.f);
    }
    __syncthreads();
    if (t < 2) {
        float a = fc2b[t];
#pragma unroll
        for (int i = 0; i < 32; i++) a = fmaf(z1[i], fc2W[i * 2 + t], a);
        z2[t] = a;
    }
    __syncthreads();
    if (t == 0) {
        float m = fmaxf(z2[0], z2[1]);
        float e0 = __expf(z2[0] - m), e1 = __expf(z2[1] - m);
        float inv = 1.f / (e0 + e1);
        out[0] = e0 * inv;
        out[1] = e1 * inv;
    }
}

// ---------------------------------------------------------------------------
extern "C" void kernel_launch(void* const* d_in, const int* in_sizes, int n_in,
                              void* d_out, int out_size) {
    const float* x    = (const float*)d_in[0];
    const int*   row  = (const int*)d_in[1];
    const int*   col  = (const int*)d_in[2];
    const float* ev   = (const float*)d_in[3];
    const float* W1   = (const float*)d_in[4];
    const float* b1   = (const float*)d_in[5];
    const float* W2   = (const float*)d_in[6];
    const float* b2   = (const float*)d_in[7];
    const float* W3   = (const float*)d_in[8];
    const float* b3   = (const float*)d_in[9];
    const float* fc1W = (const float*)d_in[10];
    const float* fc1b = (const float*)d_in[11];
    const float* fc2W = (const float*)d_in[12];
    const float* fc2b = (const float*)d_in[13];
    float* out = (float*)d_out;

    int N = in_sizes[0] / 256;   // NFEAT = 256
    int E = in_sizes[1];

    int nbN   = (N + 255) / 256;                 // 391
    int gG    = (N + 127) / 128;                 // 782 (gemm1 128-node tiles)
    int gG2   = (N + 127) / 128;                 // 782
    int cntB  = (E + 1023) / 1024;               // 1563
    int fillB = (E / 2 + 255) / 256;             // 3125
    int spB   = (N * 8 + 255) / 256;             // 3125

    count_kernel<<<cntB, 256>>>(row, E);
    scan_kernel<<<nbN, 256>>>(N);
    gemm1_fill_kernel<<<gG + fillB, 256>>>(x, W1, row, col, ev, N, gG, E);

    spmm_kernel<32><<<spB, 256>>>(b1, N);
    gemm_tc_kernel<32, 48><<<gG2, 256>>>(W2, N);
    spmm_kernel<48><<<spB, 256>>>(b2, N);
    gemm_tc_kernel<48, 64><<<gG2, 256>>>(W3, N);
    spmm3_pool_kernel<<<1184, 256>>>(b3, N);
    head_kernel<<<1, 64>>>(fc1W, fc1b, fc2W, fc2b, out, 1.0f / (float)N);
}